// round 12
// baseline (speedup 1.0000x reference)
#include <cuda_runtime.h>
#include <cuda_fp16.h>
#include <cstdint>

// ---------------------------------------------------------------------------
// Problem constants
// ---------------------------------------------------------------------------
#define SEQ    2048
#define BATCH  8
#define DMODEL 512
#define HEADS  8
#define DK     64
#define DFF    2048
#define TTOK   (SEQ * BATCH)          // 16384 tokens, t = s*BATCH + b
#define NQVR   (3 * DMODEL)           // 1536 fused projection width

// ---------------------------------------------------------------------------
// Device scratch (static; cudaMalloc forbidden)
// ---------------------------------------------------------------------------
__device__ __half g_xh   [TTOK * DMODEL];
__device__ __half g_QVRh [TTOK * NQVR];    // fused Q|V|R, token stride 1536
__device__ __half g_Hh   [TTOK * DMODEL];
__device__ __half g_attnh[TTOK * DMODEL];
__device__ __half g_x1h  [TTOK * DMODEL];
__device__ __half g_ffh  [TTOK * DFF];
__device__ float  g_tmp  [TTOK * DMODEL];
__device__ float  g_x1   [TTOK * DMODEL];
__device__ __half g_Wqvrh[NQVR * DMODEL];  // [1536][512]: Wq rows 0-511, Wv 512-1023, Wr 1024-1535
__device__ float  g_bqvr [NQVR];
__device__ __half g_Woh  [DMODEL * DMODEL];
__device__ __half g_Wf1T [DFF * DMODEL];   // [2048][512] half
__device__ __half g_Wf2T [DMODEL * DFF];   // [512][2048] half

// ---------------------------------------------------------------------------
// Helpers
// ---------------------------------------------------------------------------
__device__ __forceinline__ uint32_t smem_u32(const void* p) {
    uint32_t a;
    asm("{ .reg .u64 t; cvta.to.shared.u64 t, %1; cvt.u32.u64 %0, t; }"
        : "=r"(a) : "l"(p));
    return a;
}
__device__ __forceinline__ void cp16(uint32_t dst, const void* src) {
    asm volatile("cp.async.cg.shared.global [%0], [%1], 16;"
                 :: "r"(dst), "l"(src));
}
__device__ __forceinline__ void cp_commit() {
    asm volatile("cp.async.commit_group;" ::: "memory");
}
__device__ __forceinline__ void cp_wait1() {
    asm volatile("cp.async.wait_group 1;" ::: "memory");
}
__device__ __forceinline__ void cp_wait0() {
    asm volatile("cp.async.wait_group 0;" ::: "memory");
}
__device__ __forceinline__ void mma_f16(float c[4],
                                        uint32_t a0, uint32_t a1, uint32_t a2, uint32_t a3,
                                        uint32_t b0, uint32_t b1) {
    asm volatile(
        "mma.sync.aligned.m16n8k16.row.col.f32.f16.f16.f32 "
        "{%0,%1,%2,%3}, {%4,%5,%6,%7}, {%8,%9}, {%0,%1,%2,%3};\n"
        : "+f"(c[0]), "+f"(c[1]), "+f"(c[2]), "+f"(c[3])
        : "r"(a0), "r"(a1), "r"(a2), "r"(a3), "r"(b0), "r"(b1));
}
__device__ __forceinline__ void ldsm_x4(uint32_t& r0, uint32_t& r1,
                                        uint32_t& r2, uint32_t& r3, uint32_t addr) {
    asm volatile("ldmatrix.sync.aligned.m8n8.x4.shared.b16 {%0,%1,%2,%3}, [%4];"
                 : "=r"(r0), "=r"(r1), "=r"(r2), "=r"(r3) : "r"(addr));
}
__device__ __forceinline__ uint32_t ldh2(const __half* p) {
    return *(const uint32_t*)p;
}
__device__ __forceinline__ uint32_t ex2_f16x2(uint32_t h2) {
    uint32_t r;
    asm("ex2.approx.f16x2 %0, %1;" : "=r"(r) : "r"(h2));
    return r;
}

// ---------------------------------------------------------------------------
// fp16 GEMM (frozen from R11):
// C[M,N] = A[M,K] @ W^T + bias, A/W half, W is [N][K] row-major.
// Block 128x128, 128 threads (4 warps, 2x2), warp tile 64x64, BK=64.
// ---------------------------------------------------------------------------
#define GP        72                         // pitch in halfs (144 B)
#define G_AH      (128 * GP)                 // 9216 halfs per A tile
#define G_STAGEH  (2 * G_AH)                 // 18432 halfs (A + B)
#define GEMM_SMEM (3 * G_STAGEH * 2)         // 110592 B

template<bool RELU, bool OUTH>
__global__ void __launch_bounds__(128, 2)
gemm_h(const __half* __restrict__ A, const __half* __restrict__ W,
       const float* __restrict__ bias, void* __restrict__ Cout,
       int M, int N, int K)
{
    extern __shared__ __half sh[];
    const int tid  = threadIdx.x;
    const int warp = tid >> 5, lane = tid & 31;
    const int g = lane >> 2, t = lane & 3;
    const int bm = blockIdx.y * 128;
    const int bn = blockIdx.x * 128;
    const int wm = (warp >> 1) * 64;
    const int wn = (warp &  1) * 64;

    const uint32_t sbase = smem_u32(sh);

    float acc[4][8][4] = {};
    const int KT = K >> 6;   // k-tiles of 64 halfs

    auto fill = [&](int s, int kt) {
        const int k0 = kt << 6;
        const uint32_t st = sbase + (uint32_t)(s * G_STAGEH) * 2;
        #pragma unroll
        for (int i = 0; i < 8; i++) {
            const int idx = tid + i * 128;           // 0..1023
            const int r   = idx >> 3;                // 0..127
            const int kq  = (idx & 7) << 3;          // 0,8,...,56
            cp16(st + (uint32_t)(r * GP + kq) * 2,
                 A + (size_t)(bm + r) * K + k0 + kq);
            cp16(st + (uint32_t)(G_AH + r * GP + kq) * 2,
                 W + (size_t)(bn + r) * K + k0 + kq);
        }
        cp_commit();
    };

    fill(0, 0);
    fill(1, 1);

    for (int kt = 0; kt < KT; kt++) {
        if (kt + 1 < KT) cp_wait1(); else cp_wait0();
        __syncthreads();

        if (kt + 2 < KT) fill((kt + 2) % 3, kt + 2);

        const uint32_t sa = sbase + (uint32_t)((kt % 3) * G_STAGEH) * 2;
        const uint32_t sb = sa + (uint32_t)G_AH * 2;

        #pragma unroll
        for (int kk = 0; kk < 64; kk += 16) {
            uint32_t af[4][4], bf[8][2];
            #pragma unroll
            for (int mt = 0; mt < 4; mt++) {
                const uint32_t addr = sa +
                    (uint32_t)((wm + mt * 16 + (lane & 15)) * GP +
                               kk + (lane >> 4) * 8) * 2;
                ldsm_x4(af[mt][0], af[mt][1], af[mt][2], af[mt][3], addr);
            }
            #pragma unroll
            for (int np = 0; np < 4; np++) {
                const uint32_t addr = sb +
                    (uint32_t)((wn + np * 16 + (lane & 7) + ((lane >> 4) << 3)) * GP +
                               kk + ((lane >> 3) & 1) * 8) * 2;
                ldsm_x4(bf[2 * np][0], bf[2 * np][1],
                        bf[2 * np + 1][0], bf[2 * np + 1][1], addr);
            }
            #pragma unroll
            for (int mt = 0; mt < 4; mt++)
                #pragma unroll
                for (int nt = 0; nt < 8; nt++)
                    mma_f16(acc[mt][nt], af[mt][0], af[mt][1], af[mt][2], af[mt][3],
                            bf[nt][0], bf[nt][1]);
        }
        __syncthreads();
    }

    #pragma unroll
    for (int mt = 0; mt < 4; mt++) {
        const int r0 = bm + wm + mt * 16 + g;
        #pragma unroll
        for (int nt = 0; nt < 8; nt++) {
            const int c = bn + wn + nt * 8 + 2 * t;
            float v0 = acc[mt][nt][0] + bias[c];
            float v1 = acc[mt][nt][1] + bias[c + 1];
            float v2 = acc[mt][nt][2] + bias[c];
            float v3 = acc[mt][nt][3] + bias[c + 1];
            if (RELU) {
                v0 = fmaxf(v0, 0.f); v1 = fmaxf(v1, 0.f);
                v2 = fmaxf(v2, 0.f); v3 = fmaxf(v3, 0.f);
            }
            if (OUTH) {
                __half* C = (__half*)Cout;
                *(__half2*)&C[(size_t)r0 * N + c]       = __floats2half2_rn(v0, v1);
                *(__half2*)&C[(size_t)(r0 + 8) * N + c] = __floats2half2_rn(v2, v3);
            } else {
                float* C = (float*)Cout;
                *(float2*)&C[(size_t)r0 * N + c]       = make_float2(v0, v1);
                *(float2*)&C[(size_t)(r0 + 8) * N + c] = make_float2(v2, v3);
            }
        }
    }
}

// ---------------------------------------------------------------------------
// fp32 -> fp16 conversion (vectorized)
// ---------------------------------------------------------------------------
__global__ void __launch_bounds__(256)
f2h_kernel(const float* __restrict__ in, __half* __restrict__ out, int n)
{
    const int i = (blockIdx.x * blockDim.x + threadIdx.x) * 4;
    if (i < n) {
        float4 v = *(const float4*)(in + i);
        *(__half2*)(out + i)     = __floats2half2_rn(v.x, v.y);
        *(__half2*)(out + i + 2) = __floats2half2_rn(v.z, v.w);
    }
}

// ---------------------------------------------------------------------------
// Transpose + convert: out[c][r] = half(in[r][c]), in fp32 [R][Cc]
// ---------------------------------------------------------------------------
__global__ void __launch_bounds__(256)
transpose_h_kernel(const float* __restrict__ in, __half* __restrict__ out,
                   int R, int Cc)
{
    __shared__ float tile[32][33];
    const int c0 = blockIdx.x * 32, r0 = blockIdx.y * 32;
    const int tx = threadIdx.x & 31, ty = threadIdx.x >> 5;   // 32x8
    #pragma unroll
    for (int i = 0; i < 4; i++)
        tile[ty + i * 8][tx] = in[(size_t)(r0 + ty + i * 8) * Cc + c0 + tx];
    __syncthreads();
    #pragma unroll
    for (int i = 0; i < 4; i++)
        out[(size_t)(c0 + ty + i * 8) * R + r0 + tx] =
            __float2half_rn(tile[tx][ty + i * 8]);
}

// ---------------------------------------------------------------------------
// Recurrence: h_t = tanh(h_{t-1} * w_diag + r_t), lane-parallel, half I/O.
// Reads R from fused QVR buffer (token stride NQVR), writes H (stride DMODEL).
// Grid 32x128 to spread the MUFU chain over 32 SMs (1 warp/SMSP).
// ---------------------------------------------------------------------------
__global__ void recur_kernel(const __half* __restrict__ R,
                             const float* __restrict__ W_h,
                             __half* __restrict__ Hout)
{
    const int gid = blockIdx.x * blockDim.x + threadIdx.x;  // 0..4095
    if (gid >= BATCH * DMODEL) return;
    const int b  = gid >> 9;
    const int hn = gid & 511;

    float w = 0.f;
    const float* wrow = W_h + (size_t)hn * DK;
    #pragma unroll
    for (int k = 0; k < DK; k++) w += wrow[k];

    float hstate = 0.f;
    size_t ridx = (size_t)b * NQVR + hn;
    size_t hidx = (size_t)b * DMODEL + hn;
    #pragma unroll 8
    for (int s = 0; s < SEQ; s++) {
        const float r = __half2float(R[ridx]);
        float x = fmaf(hstate, w, r);
        asm("tanh.approx.f32 %0, %1;" : "=f"(hstate) : "f"(x));
        Hout[hidx] = __float2half_rn(hstate);
        ridx += (size_t)BATCH * NQVR;
        hidx += (size_t)BATCH * DMODEL;
    }
}

// ---------------------------------------------------------------------------
// Flash attention v6: q-tile 256 (8 warps, 256 thr, 32 q/warp), key-tile 64.
// Q/V read from fused QVR buffer (token stride NQVR); K from H (stride DMODEL).
// Register-resident P (ex2.f16x2 outputs ARE the PV A-fragments);
// XOR-swizzled Vt staging. scores = (Q.K)*0.125 + (k>q ? 1.0 : 0.0)
// ---------------------------------------------------------------------------
#define AP       72
#define QS_OFF   0
#define KS_OFF   (256 * AP)
#define VT_OFF   (KS_OFF + 64 * AP)
#define ATTN_SMEM ((VT_OFF + 64 * AP) * 2)   // 55296 B
#define L2E      1.44269504089f

__global__ void __launch_bounds__(256)
attn_h(const __half* __restrict__ Q, const __half* __restrict__ Hk,
       const __half* __restrict__ V, __half* __restrict__ O)
{
    extern __shared__ __half sh[];
    __half (*Qs)[AP] = (__half(*)[AP])(sh + QS_OFF);
    __half (*Ks)[AP] = (__half(*)[AP])(sh + KS_OFF);
    __half (*Vt)[AP] = (__half(*)[AP])(sh + VT_OFF);

    const int tid  = threadIdx.x;
    const int warp = tid >> 5, lane = tid & 31;
    const int g = lane >> 2, t = lane & 3;
    const int bh = blockIdx.y;
    const int b  = bh >> 3, h = bh & 7;
    const int q0 = blockIdx.x << 8;          // 256 q rows per block

    // ---- stage Q tile (256 rows x 64 halfs) ----
    #pragma unroll
    for (int i = 0; i < 8; i++) {
        const int idx = tid + i * 256;       // 0..2047 8-half chunks
        const int r   = idx >> 3;            // 0..255
        const int dq  = (idx & 7) * 8;       // 0..56
        const size_t ga = ((size_t)(q0 + r) * BATCH + b) * NQVR + h * DK + dq;
        *(float4*)&Qs[r][dq] = *(const float4*)&Q[ga];
    }

    float o[2][8][4] = {};
    float mrow[4] = {-1e30f, -1e30f, -1e30f, -1e30f};
    float lrow[4] = {0.f, 0.f, 0.f, 0.f};
    const float scale = 0.125f;

    __syncthreads();

    for (int k0 = 0; k0 < SEQ; k0 += 64) {
        // ---- stage K tile + V tile (XOR-swizzled transpose) ----
        #pragma unroll
        for (int i = 0; i < 2; i++) {
            const int idx = tid + i * 256;   // 0..511
            const int r   = idx >> 3;        // 0..63 (key)
            const int dq  = (idx & 7) * 8;   // 0..56
            const size_t kga = ((size_t)(k0 + r) * BATCH + b) * DMODEL + h * DK + dq;
            *(float4*)&Ks[r][dq] = *(const float4*)&Hk[kga];
            const size_t vga = ((size_t)(k0 + r) * BATCH + b) * NQVR + h * DK + dq;
            const __half* vp = &V[vga];
            #pragma unroll
            for (int j = 0; j < 8; j++)
                Vt[dq + j][r ^ dq] = vp[j];   // (dq+j)&56 == dq for j<8
        }
        __syncthreads();

        #pragma unroll
        for (int mt = 0; mt < 2; mt++) {
            const int qrow = warp * 32 + mt * 16;

            // ---- S = Q @ K^T  (16q x 64k, d=64 in 4 k16 steps) ----
            float s[8][4] = {};
            #pragma unroll
            for (int kk = 0; kk < 64; kk += 16) {
                const uint32_t a0 = ldh2(&Qs[qrow + g    ][kk + 2 * t    ]);
                const uint32_t a1 = ldh2(&Qs[qrow + 8 + g][kk + 2 * t    ]);
                const uint32_t a2 = ldh2(&Qs[qrow + g    ][kk + 2 * t + 8]);
                const uint32_t a3 = ldh2(&Qs[qrow + 8 + g][kk + 2 * t + 8]);
                #pragma unroll
                for (int nt = 0; nt < 8; nt++) {
                    const uint32_t b0 = ldh2(&Ks[nt * 8 + g][kk + 2 * t    ]);
                    const uint32_t b1 = ldh2(&Ks[nt * 8 + g][kk + 2 * t + 8]);
                    mma_f16(s[nt], a0, a1, a2, a3, b0, b1);
                }
            }

            // ---- scale + mask ----
            const int qg0 = q0 + qrow + g;
            #pragma unroll
            for (int nt = 0; nt < 8; nt++) {
                const int kg = k0 + nt * 8 + 2 * t;
                s[nt][0] = s[nt][0] * scale + ((kg     > qg0    ) ? 1.f : 0.f);
                s[nt][1] = s[nt][1] * scale + ((kg + 1 > qg0    ) ? 1.f : 0.f);
                s[nt][2] = s[nt][2] * scale + ((kg     > qg0 + 8) ? 1.f : 0.f);
                s[nt][3] = s[nt][3] * scale + ((kg + 1 > qg0 + 8) ? 1.f : 0.f);
            }

            // ---- online softmax (rows g, g+8), packed f16x2 ex2 ----
            uint32_t p2[8][2];   // exp results as half2 == PV A-fragments
            #pragma unroll
            for (int half_i = 0; half_i < 2; half_i++) {
                const int ri = mt * 2 + half_i;
                float tm = -1e30f;
                #pragma unroll
                for (int nt = 0; nt < 8; nt++) {
                    tm = fmaxf(tm, s[nt][2 * half_i]);
                    tm = fmaxf(tm, s[nt][2 * half_i + 1]);
                }
                tm = fmaxf(tm, __shfl_xor_sync(0xffffffffu, tm, 1));
                tm = fmaxf(tm, __shfl_xor_sync(0xffffffffu, tm, 2));
                const float mnew = fmaxf(mrow[ri], tm);
                const float corr = __expf(mrow[ri] - mnew);
                const float mnL  = mnew * L2E;
                float ts = 0.f;
                #pragma unroll
                for (int nt = 0; nt < 8; nt++) {
                    const float a0 = fmaf(s[nt][2 * half_i],     L2E, -mnL);
                    const float a1 = fmaf(s[nt][2 * half_i + 1], L2E, -mnL);
                    __half2 hh = __floats2half2_rn(a0, a1);
                    const uint32_t pe = ex2_f16x2(*(uint32_t*)&hh);
                    p2[nt][half_i] = pe;
                    const float2 f = __half22float2(*(__half2*)&pe);
                    ts += f.x + f.y;
                }
                ts += __shfl_xor_sync(0xffffffffu, ts, 1);
                ts += __shfl_xor_sync(0xffffffffu, ts, 2);
                lrow[ri] = lrow[ri] * corr + ts;
                mrow[ri] = mnew;
                #pragma unroll
                for (int nt = 0; nt < 8; nt++) {
                    o[mt][nt][2 * half_i]     *= corr;
                    o[mt][nt][2 * half_i + 1] *= corr;
                }
            }

            // ---- O += P @ V : p2 used directly as A-fragments ----
            #pragma unroll
            for (int j = 0; j < 4; j++) {
                const uint32_t a0 = p2[2 * j][0];
                const uint32_t a1 = p2[2 * j][1];
                const uint32_t a2 = p2[2 * j + 1][0];
                const uint32_t a3 = p2[2 * j + 1][1];
                #pragma unroll
                for (int nt = 0; nt < 8; nt++) {
                    const int row = nt * 8 + g;
                    const int sw  = nt * 8;           // row & 56 (g < 8)
                    const uint32_t b0 = ldh2(&Vt[row][(j * 16 + 2 * t    ) ^ sw]);
                    const uint32_t b1 = ldh2(&Vt[row][(j * 16 + 2 * t + 8) ^ sw]);
                    mma_f16(o[mt][nt], a0, a1, a2, a3, b0, b1);
                }
            }
        }
        __syncthreads();   // protect Ks/Vt for next tile
    }

    // ---- epilogue: normalize & store half ----
    #pragma unroll
    for (int mt = 0; mt < 2; mt++) {
        const float inv0 = 1.f / lrow[mt * 2];
        const float inv1 = 1.f / lrow[mt * 2 + 1];
        const int r0 = q0 + warp * 32 + mt * 16 + g;
        #pragma unroll
        for (int nt = 0; nt < 8; nt++) {
            const int c = h * DK + nt * 8 + 2 * t;
            *(__half2*)&O[((size_t)r0 * BATCH + b) * DMODEL + c] =
                __floats2half2_rn(o[mt][nt][0] * inv0, o[mt][nt][1] * inv0);
            *(__half2*)&O[((size_t)(r0 + 8) * BATCH + b) * DMODEL + c] =
                __floats2half2_rn(o[mt][nt][2] * inv1, o[mt][nt][3] * inv1);
        }
    }
}

// ---------------------------------------------------------------------------
// Fused residual-add + LayerNorm; optional half copy of the output.
// ---------------------------------------------------------------------------
__global__ void __launch_bounds__(256)
add_ln_kernel(const float* __restrict__ X, const float* __restrict__ Y,
              const float* __restrict__ gamma, const float* __restrict__ beta,
              float* __restrict__ out, __half* __restrict__ outh)
{
    const int warp = (blockIdx.x * blockDim.x + threadIdx.x) >> 5;
    const int lane = threadIdx.x & 31;
    if (warp >= TTOK) return;

    const float* xr = X + (size_t)warp * DMODEL;
    const float* yr = Y + (size_t)warp * DMODEL;

    float v[16];
    float sum = 0.f;
    #pragma unroll
    for (int i = 0; i < 16; i++) {
        v[i] = xr[lane + i * 32] + yr[lane + i * 32];
        sum += v[i];
    }
    #pragma unroll
    for (int m = 16; m > 0; m >>= 1) sum += __shfl_xor_sync(0xffffffffu, sum, m);
    const float mu = sum * (1.f / DMODEL);

    float var = 0.f;
    #pragma unroll
    for (int i = 0; i < 16; i++) { const float d = v[i] - mu; var = fmaf(d, d, var); }
    #pragma unroll
    for (int m = 16; m > 0; m >>= 1) var += __shfl_xor_sync(0xffffffffu, var, m);
    const float rstd = rsqrtf(var * (1.f / DMODEL) + 1e-5f);

    float* orow = out + (size_t)warp * DMODEL;
    #pragma unroll
    for (int i = 0; i < 16; i++) {
        const int c = lane + i * 32;
        const float val = (v[i] - mu) * rstd * gamma[c] + beta[c];
        orow[c] = val;
        if (outh) outh[(size_t)warp * DMODEL + c] = __float2half_rn(val);
    }
}

// ---------------------------------------------------------------------------
// Launch orchestration
// ---------------------------------------------------------------------------
extern "C" void kernel_launch(void* const* d_in, const int* in_sizes, int n_in,
                              void* d_out, int out_size)
{
    const float* x     = (const float*)d_in[0];
    const float* Wq    = (const float*)d_in[1];
    const float* bq    = (const float*)d_in[2];
    const float* Wv    = (const float*)d_in[3];
    const float* bv    = (const float*)d_in[4];
    const float* Wr    = (const float*)d_in[5];
    const float* br    = (const float*)d_in[6];
    const float* W_h   = (const float*)d_in[7];
    const float* Wo    = (const float*)d_in[8];
    const float* bo    = (const float*)d_in[9];
    const float* ln1_g = (const float*)d_in[10];
    const float* ln1_b = (const float*)d_in[11];
    const float* Wf1   = (const float*)d_in[12];
    const float* bf1   = (const float*)d_in[13];
    const float* Wf2   = (const float*)d_in[14];
    const float* bf2   = (const float*)d_in[15];
    const float* ln2_g = (const float*)d_in[16];
    const float* ln2_b = (const float*)d_in[17];
    float* out = (float*)d_out;

    static __half *pxh = nullptr, *pQVR, *pHh, *pAh, *px1h, *pFFh,
                  *pWqvr, *pWoh, *pW1T, *pW2T;
    static float *pTmp, *pX1, *pbqvr;
    if (!pxh) {
        cudaGetSymbolAddress((void**)&pxh,   g_xh);
        cudaGetSymbolAddress((void**)&pQVR,  g_QVRh);
        cudaGetSymbolAddress((void**)&pHh,   g_Hh);
        cudaGetSymbolAddress((void**)&pAh,   g_attnh);
        cudaGetSymbolAddress((void**)&px1h,  g_x1h);
        cudaGetSymbolAddress((void**)&pFFh,  g_ffh);
        cudaGetSymbolAddress((void**)&pWqvr, g_Wqvrh);
        cudaGetSymbolAddress((void**)&pbqvr, g_bqvr);
        cudaGetSymbolAddress((void**)&pWoh,  g_Woh);
        cudaGetSymbolAddress((void**)&pW1T,  g_Wf1T);
        cudaGetSymbolAddress((void**)&pW2T,  g_Wf2T);
        cudaGetSymbolAddress((void**)&pTmp,  g_tmp);
        cudaGetSymbolAddress((void**)&pX1,   g_x1);
        cudaFuncSetAttribute(attn_h, cudaFuncAttributeMaxDynamicSharedMemorySize,
                             ATTN_SMEM);
        cudaFuncSetAttribute(gemm_h<false, true>,
                             cudaFuncAttributeMaxDynamicSharedMemorySize, GEMM_SMEM);
        cudaFuncSetAttribute(gemm_h<false, false>,
                             cudaFuncAttributeMaxDynamicSharedMemorySize, GEMM_SMEM);
        cudaFuncSetAttribute(gemm_h<true, true>,
                             cudaFuncAttributeMaxDynamicSharedMemorySize, GEMM_SMEM);
    }

    const dim3 gQVR(NQVR  / 128, TTOK / 128);   // (12, 128) fused projection
    const dim3 gP  (DMODEL / 128, TTOK / 128);  // (4, 128)
    const dim3 gF1 (DFF    / 128, TTOK / 128);  // (16, 128)
    const dim3 gAt (SEQ / 256, BATCH * HEADS);  // (8, 64)
    const dim3 gLN (TTOK / 8, 1);

    const int WSZ = DMODEL * DMODEL;            // 262144

    // 0a) conversions: x and fused Wq|Wv|Wr weight block; biases via D2D copies
    f2h_kernel<<<(TTOK * DMODEL / 4 + 255) / 256, 256>>>(x, pxh, TTOK * DMODEL);
    f2h_kernel<<<(WSZ / 4 + 255) / 256, 256>>>(Wq, pWqvr, WSZ);
    f2h_kernel<<<(WSZ / 4 + 255) / 256, 256>>>(Wv, pWqvr + WSZ, WSZ);
    f2h_kernel<<<(WSZ / 4 + 255) / 256, 256>>>(Wr, pWqvr + 2 * WSZ, WSZ);
    cudaMemcpyAsync(pbqvr,              bq, DMODEL * sizeof(float),
                    cudaMemcpyDeviceToDevice);
    cudaMemcpyAsync(pbqvr + DMODEL,     bv, DMODEL * sizeof(float),
                    cudaMemcpyDeviceToDevice);
    cudaMemcpyAsync(pbqvr + 2 * DMODEL, br, DMODEL * sizeof(float),
                    cudaMemcpyDeviceToDevice);

    // 1) fused Q|V|R projection -> g_QVRh [TTOK][1536]
    gemm_h<false, true><<<gQVR, 128, GEMM_SMEM>>>(pxh, pWqvr, pbqvr, pQVR,
                                                  TTOK, NQVR, DMODEL);

    // 2) recurrence -> keys H (reads R at column offset 1024)
    recur_kernel<<<32, 128>>>(pQVR + 2 * DMODEL, W_h, pHh);

    // 3) attention (Q at offset 0, V at offset 512 in fused buffer)
    attn_h<<<gAt, 256, ATTN_SMEM>>>(pQVR, pHh, pQVR + DMODEL, pAh);

    // 0b) deferred conversions (needed from step 4 onward)
    f2h_kernel<<<(WSZ / 4 + 255) / 256, 256>>>(Wo, pWoh, WSZ);
    transpose_h_kernel<<<dim3(DFF / 32, DMODEL / 32), 256>>>(Wf1, pW1T, DMODEL, DFF);
    transpose_h_kernel<<<dim3(DMODEL / 32, DFF / 32), 256>>>(Wf2, pW2T, DFF, DMODEL);

    // 4) output projection (fp32 out, feeds LN)
    gemm_h<false, false><<<gP, 128, GEMM_SMEM>>>(pAh, pWoh, bo, pTmp, TTOK, DMODEL, DMODEL);

    // 5) x1 = LN1(x + attn_proj): fp32 + half copies
    add_ln_kernel<<<gLN, 256>>>(x, pTmp, ln1_g, ln1_b, pX1, px1h);

    // 6) ff = relu(x1 @ Wf1 + bf1) (half out)
    gemm_h<true, true><<<gF1, 128, GEMM_SMEM>>>(px1h, pW1T, bf1, pFFh, TTOK, DFF, DMODEL);

    // 7) ff2 = ff @ Wf2 + bf2 (fp32 out, feeds LN)
    gemm_h<false, false><<<gP, 128, GEMM_SMEM>>>(pFFh, pW2T, bf2, pTmp, TTOK, DMODEL, DFF);

    // 8) out = LN2(x1 + ff2)
    add_ln_kernel<<<gLN, 256>>>(pX1, pTmp, ln2_g, ln2_b, out, nullptr);
}

// round 13
// speedup vs baseline: 1.1480x; 1.1480x over previous
#include <cuda_runtime.h>
#include <cuda_fp16.h>
#include <cstdint>

// ---------------------------------------------------------------------------
// Problem constants
// ---------------------------------------------------------------------------
#define SEQ    2048
#define BATCH  8
#define DMODEL 512
#define HEADS  8
#define DK     64
#define DFF    2048
#define TTOK   (SEQ * BATCH)          // 16384 tokens, t = s*BATCH + b

// ---------------------------------------------------------------------------
// Device scratch (static; cudaMalloc forbidden)
// ---------------------------------------------------------------------------
__device__ __half g_xh  [TTOK * DMODEL];
__device__ __half g_Qh  [TTOK * DMODEL];
__device__ __half g_Vh  [TTOK * DMODEL];
__device__ __half g_Rh  [TTOK * DMODEL];
__device__ __half g_Hh  [TTOK * DMODEL];
__device__ __half g_attnh[TTOK * DMODEL];
__device__ __half g_x1h [TTOK * DMODEL];
__device__ __half g_ffh [TTOK * DFF];
__device__ float  g_tmp [TTOK * DMODEL];
__device__ float  g_x1  [TTOK * DMODEL];
__device__ __half g_Wqh [DMODEL * DMODEL];
__device__ __half g_Wvh [DMODEL * DMODEL];
__device__ __half g_Wrh [DMODEL * DMODEL];
__device__ __half g_Woh [DMODEL * DMODEL];
__device__ __half g_Wf1T[DFF * DMODEL];   // [2048][512] half
__device__ __half g_Wf2T[DMODEL * DFF];   // [512][2048] half

// ---------------------------------------------------------------------------
// Helpers
// ---------------------------------------------------------------------------
__device__ __forceinline__ uint32_t smem_u32(const void* p) {
    uint32_t a;
    asm("{ .reg .u64 t; cvta.to.shared.u64 t, %1; cvt.u32.u64 %0, t; }"
        : "=r"(a) : "l"(p));
    return a;
}
__device__ __forceinline__ void cp16(uint32_t dst, const void* src) {
    asm volatile("cp.async.cg.shared.global [%0], [%1], 16;"
                 :: "r"(dst), "l"(src));
}
__device__ __forceinline__ void cp_commit() {
    asm volatile("cp.async.commit_group;" ::: "memory");
}
__device__ __forceinline__ void cp_wait1() {
    asm volatile("cp.async.wait_group 1;" ::: "memory");
}
__device__ __forceinline__ void cp_wait0() {
    asm volatile("cp.async.wait_group 0;" ::: "memory");
}
__device__ __forceinline__ void mma_f16(float c[4],
                                        uint32_t a0, uint32_t a1, uint32_t a2, uint32_t a3,
                                        uint32_t b0, uint32_t b1) {
    asm volatile(
        "mma.sync.aligned.m16n8k16.row.col.f32.f16.f16.f32 "
        "{%0,%1,%2,%3}, {%4,%5,%6,%7}, {%8,%9}, {%0,%1,%2,%3};\n"
        : "+f"(c[0]), "+f"(c[1]), "+f"(c[2]), "+f"(c[3])
        : "r"(a0), "r"(a1), "r"(a2), "r"(a3), "r"(b0), "r"(b1));
}
__device__ __forceinline__ void ldsm_x4(uint32_t& r0, uint32_t& r1,
                                        uint32_t& r2, uint32_t& r3, uint32_t addr) {
    asm volatile("ldmatrix.sync.aligned.m8n8.x4.shared.b16 {%0,%1,%2,%3}, [%4];"
                 : "=r"(r0), "=r"(r1), "=r"(r2), "=r"(r3) : "r"(addr));
}
__device__ __forceinline__ uint32_t ldh2(const __half* p) {
    return *(const uint32_t*)p;
}
__device__ __forceinline__ uint32_t ex2_f16x2(uint32_t h2) {
    uint32_t r;
    asm("ex2.approx.f16x2 %0, %1;" : "=r"(r) : "r"(h2));
    return r;
}

// ---------------------------------------------------------------------------
// fp16 GEMM (frozen from R11):
// C[M,N] = A[M,K] @ W^T + bias, A/W half, W is [N][K] row-major.
// Block 128x128, 128 threads (4 warps, 2x2), warp tile 64x64, BK=64.
// ---------------------------------------------------------------------------
#define GP        72                         // pitch in halfs (144 B)
#define G_AH      (128 * GP)                 // 9216 halfs per A tile
#define G_STAGEH  (2 * G_AH)                 // 18432 halfs (A + B)
#define GEMM_SMEM (3 * G_STAGEH * 2)         // 110592 B

template<bool RELU, bool OUTH>
__global__ void __launch_bounds__(128, 2)
gemm_h(const __half* __restrict__ A, const __half* __restrict__ W,
       const float* __restrict__ bias, void* __restrict__ Cout,
       int M, int N, int K)
{
    extern __shared__ __half sh[];
    const int tid  = threadIdx.x;
    const int warp = tid >> 5, lane = tid & 31;
    const int g = lane >> 2, t = lane & 3;
    const int bm = blockIdx.y * 128;
    const int bn = blockIdx.x * 128;
    const int wm = (warp >> 1) * 64;
    const int wn = (warp &  1) * 64;

    const uint32_t sbase = smem_u32(sh);

    float acc[4][8][4] = {};
    const int KT = K >> 6;   // k-tiles of 64 halfs

    auto fill = [&](int s, int kt) {
        const int k0 = kt << 6;
        const uint32_t st = sbase + (uint32_t)(s * G_STAGEH) * 2;
        #pragma unroll
        for (int i = 0; i < 8; i++) {
            const int idx = tid + i * 128;           // 0..1023
            const int r   = idx >> 3;                // 0..127
            const int kq  = (idx & 7) << 3;          // 0,8,...,56
            cp16(st + (uint32_t)(r * GP + kq) * 2,
                 A + (size_t)(bm + r) * K + k0 + kq);
            cp16(st + (uint32_t)(G_AH + r * GP + kq) * 2,
                 W + (size_t)(bn + r) * K + k0 + kq);
        }
        cp_commit();
    };

    fill(0, 0);
    fill(1, 1);

    for (int kt = 0; kt < KT; kt++) {
        if (kt + 1 < KT) cp_wait1(); else cp_wait0();
        __syncthreads();

        if (kt + 2 < KT) fill((kt + 2) % 3, kt + 2);

        const uint32_t sa = sbase + (uint32_t)((kt % 3) * G_STAGEH) * 2;
        const uint32_t sb = sa + (uint32_t)G_AH * 2;

        #pragma unroll
        for (int kk = 0; kk < 64; kk += 16) {
            uint32_t af[4][4], bf[8][2];
            #pragma unroll
            for (int mt = 0; mt < 4; mt++) {
                const uint32_t addr = sa +
                    (uint32_t)((wm + mt * 16 + (lane & 15)) * GP +
                               kk + (lane >> 4) * 8) * 2;
                ldsm_x4(af[mt][0], af[mt][1], af[mt][2], af[mt][3], addr);
            }
            #pragma unroll
            for (int np = 0; np < 4; np++) {
                const uint32_t addr = sb +
                    (uint32_t)((wn + np * 16 + (lane & 7) + ((lane >> 4) << 3)) * GP +
                               kk + ((lane >> 3) & 1) * 8) * 2;
                ldsm_x4(bf[2 * np][0], bf[2 * np][1],
                        bf[2 * np + 1][0], bf[2 * np + 1][1], addr);
            }
            #pragma unroll
            for (int mt = 0; mt < 4; mt++)
                #pragma unroll
                for (int nt = 0; nt < 8; nt++)
                    mma_f16(acc[mt][nt], af[mt][0], af[mt][1], af[mt][2], af[mt][3],
                            bf[nt][0], bf[nt][1]);
        }
        __syncthreads();
    }

    #pragma unroll
    for (int mt = 0; mt < 4; mt++) {
        const int r0 = bm + wm + mt * 16 + g;
        #pragma unroll
        for (int nt = 0; nt < 8; nt++) {
            const int c = bn + wn + nt * 8 + 2 * t;
            float v0 = acc[mt][nt][0] + bias[c];
            float v1 = acc[mt][nt][1] + bias[c + 1];
            float v2 = acc[mt][nt][2] + bias[c];
            float v3 = acc[mt][nt][3] + bias[c + 1];
            if (RELU) {
                v0 = fmaxf(v0, 0.f); v1 = fmaxf(v1, 0.f);
                v2 = fmaxf(v2, 0.f); v3 = fmaxf(v3, 0.f);
            }
            if (OUTH) {
                __half* C = (__half*)Cout;
                *(__half2*)&C[(size_t)r0 * N + c]       = __floats2half2_rn(v0, v1);
                *(__half2*)&C[(size_t)(r0 + 8) * N + c] = __floats2half2_rn(v2, v3);
            } else {
                float* C = (float*)Cout;
                *(float2*)&C[(size_t)r0 * N + c]       = make_float2(v0, v1);
                *(float2*)&C[(size_t)(r0 + 8) * N + c] = make_float2(v2, v3);
            }
        }
    }
}

// ---------------------------------------------------------------------------
// fp32 -> fp16 conversion (vectorized)
// ---------------------------------------------------------------------------
__global__ void __launch_bounds__(256)
f2h_kernel(const float* __restrict__ in, __half* __restrict__ out, int n)
{
    const int i = (blockIdx.x * blockDim.x + threadIdx.x) * 4;
    if (i < n) {
        float4 v = *(const float4*)(in + i);
        *(__half2*)(out + i)     = __floats2half2_rn(v.x, v.y);
        *(__half2*)(out + i + 2) = __floats2half2_rn(v.z, v.w);
    }
}

// ---------------------------------------------------------------------------
// Transpose + convert: out[c][r] = half(in[r][c]), in fp32 [R][Cc]
// ---------------------------------------------------------------------------
__global__ void __launch_bounds__(256)
transpose_h_kernel(const float* __restrict__ in, __half* __restrict__ out,
                   int R, int Cc)
{
    __shared__ float tile[32][33];
    const int c0 = blockIdx.x * 32, r0 = blockIdx.y * 32;
    const int tx = threadIdx.x & 31, ty = threadIdx.x >> 5;   // 32x8
    #pragma unroll
    for (int i = 0; i < 4; i++)
        tile[ty + i * 8][tx] = in[(size_t)(r0 + ty + i * 8) * Cc + c0 + tx];
    __syncthreads();
    #pragma unroll
    for (int i = 0; i < 4; i++)
        out[(size_t)(c0 + ty + i * 8) * R + r0 + tx] =
            __float2half_rn(tile[tx][ty + i * 8]);
}

// ---------------------------------------------------------------------------
// Recurrence: h_t = tanh(h_{t-1} * w_diag + r_t), lane-parallel, half I/O.
// ---------------------------------------------------------------------------
__global__ void recur_kernel(const __half* __restrict__ R,
                             const float* __restrict__ W_h,
                             __half* __restrict__ Hout)
{
    const int gid = blockIdx.x * blockDim.x + threadIdx.x;  // 0..4095
    if (gid >= BATCH * DMODEL) return;
    const int b  = gid >> 9;
    const int hn = gid & 511;

    float w = 0.f;
    const float* wrow = W_h + (size_t)hn * DK;
    #pragma unroll
    for (int k = 0; k < DK; k++) w += wrow[k];

    float hstate = 0.f;
    const size_t stride = (size_t)BATCH * DMODEL;
    size_t idx = (size_t)b * DMODEL + hn;
    #pragma unroll 8
    for (int s = 0; s < SEQ; s++) {
        const float r = __half2float(R[idx]);
        float x = fmaf(hstate, w, r);
        asm("tanh.approx.f32 %0, %1;" : "=f"(hstate) : "f"(x));
        Hout[idx] = __float2half_rn(hstate);
        idx += stride;
    }
}

// ---------------------------------------------------------------------------
// Flash attention v7 (R11 + software-pipelined global loads):
// Next tile's K/V are LDG'd into registers DURING current-tile compute;
// only the STS phase stays on the critical path.
// 4 warps, q-tile 128 (32 q/warp), key-tile 64.
// Qs/Ks: [row][d/key] pitch 72; Vt: [d][key ^ (d&56)] pitch 72.
// Register-resident P (ex2.f16x2 outputs ARE the PV A-fragments).
// scores = (Q.K)*0.125 + (k>q ? 1.0 : 0.0)
// ---------------------------------------------------------------------------
#define AP       72
#define QS_OFF   0
#define KS_OFF   (128 * AP)
#define VT_OFF   (KS_OFF + 64 * AP)
#define ATTN_SMEM ((VT_OFF + 64 * AP) * 2)   // 36864 B
#define L2E      1.44269504089f

__global__ void __launch_bounds__(128)
attn_h(const __half* __restrict__ Q, const __half* __restrict__ Hk,
       const __half* __restrict__ V, __half* __restrict__ O)
{
    extern __shared__ __half sh[];
    __half (*Qs)[AP] = (__half(*)[AP])(sh + QS_OFF);
    __half (*Ks)[AP] = (__half(*)[AP])(sh + KS_OFF);
    __half (*Vt)[AP] = (__half(*)[AP])(sh + VT_OFF);

    const int tid  = threadIdx.x;
    const int warp = tid >> 5, lane = tid & 31;
    const int g = lane >> 2, t = lane & 3;
    const int bh = blockIdx.y;
    const int b  = bh >> 3, h = bh & 7;
    const int q0 = blockIdx.x << 7;          // 128 q rows per block

    // ---- stage Q tile (128 rows x 64 halfs) ----
    #pragma unroll
    for (int i = 0; i < 8; i++) {
        const int idx = tid + i * 128;       // 0..1023 8-half chunks
        const int r   = idx >> 3;            // 0..127
        const int dq  = (idx & 7) * 8;       // 0..56
        const size_t ga = ((size_t)(q0 + r) * BATCH + b) * DMODEL + h * DK + dq;
        *(float4*)&Qs[r][dq] = *(const float4*)&Q[ga];
    }

    float o[2][8][4] = {};
    float mrow[4] = {-1e30f, -1e30f, -1e30f, -1e30f};
    float lrow[4] = {0.f, 0.f, 0.f, 0.f};
    const float scale = 0.125f;

    // per-thread staging coordinates (i-loop of 4: idx = tid + i*128)
    // r = idx>>3 (0..63), dq = (idx&7)*8
    float4 kreg[4], vreg[4];
    auto load_tile = [&](int k0) {
        #pragma unroll
        for (int i = 0; i < 4; i++) {
            const int idx = tid + i * 128;
            const int r   = idx >> 3;
            const int dq  = (idx & 7) * 8;
            const size_t ga = ((size_t)(k0 + r) * BATCH + b) * DMODEL + h * DK + dq;
            kreg[i] = *(const float4*)&Hk[ga];
            vreg[i] = *(const float4*)&V[ga];
        }
    };

    // prologue: load tile 0 into registers
    load_tile(0);
    __syncthreads();   // Qs visible

    for (int k0 = 0; k0 < SEQ; k0 += 64) {
        // ---- store staged K/V registers to smem ----
        #pragma unroll
        for (int i = 0; i < 4; i++) {
            const int idx = tid + i * 128;
            const int r   = idx >> 3;
            const int dq  = (idx & 7) * 8;
            *(float4*)&Ks[r][dq] = kreg[i];
            const __half* vp = (const __half*)&vreg[i];
            #pragma unroll
            for (int j = 0; j < 8; j++)
                Vt[dq + j][r ^ dq] = vp[j];   // (dq+j)&56 == dq for j<8
        }
        __syncthreads();

        // ---- prefetch next tile into registers (overlaps compute below) ----
        if (k0 + 64 < SEQ) load_tile(k0 + 64);

        #pragma unroll
        for (int mt = 0; mt < 2; mt++) {
            const int qrow = warp * 32 + mt * 16;

            // ---- S = Q @ K^T  (16q x 64k, d=64 in 4 k16 steps) ----
            float s[8][4] = {};
            #pragma unroll
            for (int kk = 0; kk < 64; kk += 16) {
                const uint32_t a0 = ldh2(&Qs[qrow + g    ][kk + 2 * t    ]);
                const uint32_t a1 = ldh2(&Qs[qrow + 8 + g][kk + 2 * t    ]);
                const uint32_t a2 = ldh2(&Qs[qrow + g    ][kk + 2 * t + 8]);
                const uint32_t a3 = ldh2(&Qs[qrow + 8 + g][kk + 2 * t + 8]);
                #pragma unroll
                for (int nt = 0; nt < 8; nt++) {
                    const uint32_t b0 = ldh2(&Ks[nt * 8 + g][kk + 2 * t    ]);
                    const uint32_t b1 = ldh2(&Ks[nt * 8 + g][kk + 2 * t + 8]);
                    mma_f16(s[nt], a0, a1, a2, a3, b0, b1);
                }
            }

            // ---- scale + mask ----
            const int qg0 = q0 + qrow + g;
            #pragma unroll
            for (int nt = 0; nt < 8; nt++) {
                const int kg = k0 + nt * 8 + 2 * t;
                s[nt][0] = s[nt][0] * scale + ((kg     > qg0    ) ? 1.f : 0.f);
                s[nt][1] = s[nt][1] * scale + ((kg + 1 > qg0    ) ? 1.f : 0.f);
                s[nt][2] = s[nt][2] * scale + ((kg     > qg0 + 8) ? 1.f : 0.f);
                s[nt][3] = s[nt][3] * scale + ((kg + 1 > qg0 + 8) ? 1.f : 0.f);
            }

            // ---- online softmax (rows g, g+8), packed f16x2 ex2 ----
            uint32_t p2[8][2];   // exp results as half2 == PV A-fragments
            #pragma unroll
            for (int half_i = 0; half_i < 2; half_i++) {
                const int ri = mt * 2 + half_i;
                float tm = -1e30f;
                #pragma unroll
                for (int nt = 0; nt < 8; nt++) {
                    tm = fmaxf(tm, s[nt][2 * half_i]);
                    tm = fmaxf(tm, s[nt][2 * half_i + 1]);
                }
                tm = fmaxf(tm, __shfl_xor_sync(0xffffffffu, tm, 1));
                tm = fmaxf(tm, __shfl_xor_sync(0xffffffffu, tm, 2));
                const float mnew = fmaxf(mrow[ri], tm);
                const float corr = __expf(mrow[ri] - mnew);
                const float mnL  = mnew * L2E;
                float ts = 0.f;
                #pragma unroll
                for (int nt = 0; nt < 8; nt++) {
                    const float a0 = fmaf(s[nt][2 * half_i],     L2E, -mnL);
                    const float a1 = fmaf(s[nt][2 * half_i + 1], L2E, -mnL);
                    __half2 hh = __floats2half2_rn(a0, a1);
                    const uint32_t pe = ex2_f16x2(*(uint32_t*)&hh);
                    p2[nt][half_i] = pe;
                    const float2 f = __half22float2(*(__half2*)&pe);
                    ts += f.x + f.y;
                }
                ts += __shfl_xor_sync(0xffffffffu, ts, 1);
                ts += __shfl_xor_sync(0xffffffffu, ts, 2);
                lrow[ri] = lrow[ri] * corr + ts;
                mrow[ri] = mnew;
                #pragma unroll
                for (int nt = 0; nt < 8; nt++) {
                    o[mt][nt][2 * half_i]     *= corr;
                    o[mt][nt][2 * half_i + 1] *= corr;
                }
            }

            // ---- O += P @ V : p2 used directly as A-fragments ----
            #pragma unroll
            for (int j = 0; j < 4; j++) {
                const uint32_t a0 = p2[2 * j][0];
                const uint32_t a1 = p2[2 * j][1];
                const uint32_t a2 = p2[2 * j + 1][0];
                const uint32_t a3 = p2[2 * j + 1][1];
                #pragma unroll
                for (int nt = 0; nt < 8; nt++) {
                    const int row = nt * 8 + g;
                    const int sw  = nt * 8;           // row & 56 (g < 8)
                    const uint32_t b0 = ldh2(&Vt[row][(j * 16 + 2 * t    ) ^ sw]);
                    const uint32_t b1 = ldh2(&Vt[row][(j * 16 + 2 * t + 8) ^ sw]);
                    mma_f16(o[mt][nt], a0, a1, a2, a3, b0, b1);
                }
            }
        }
        __syncthreads();   // protect Ks/Vt for next tile's store phase
    }

    // ---- epilogue: normalize & store half ----
    #pragma unroll
    for (int mt = 0; mt < 2; mt++) {
        const float inv0 = 1.f / lrow[mt * 2];
        const float inv1 = 1.f / lrow[mt * 2 + 1];
        const int r0 = q0 + warp * 32 + mt * 16 + g;
        #pragma unroll
        for (int nt = 0; nt < 8; nt++) {
            const int c = h * DK + nt * 8 + 2 * t;
            *(__half2*)&O[((size_t)r0 * BATCH + b) * DMODEL + c] =
                __floats2half2_rn(o[mt][nt][0] * inv0, o[mt][nt][1] * inv0);
            *(__half2*)&O[((size_t)(r0 + 8) * BATCH + b) * DMODEL + c] =
                __floats2half2_rn(o[mt][nt][2] * inv1, o[mt][nt][3] * inv1);
        }
    }
}

// ---------------------------------------------------------------------------
// Fused residual-add + LayerNorm; optional half copy of the output.
// ---------------------------------------------------------------------------
__global__ void __launch_bounds__(256)
add_ln_kernel(const float* __restrict__ X, const float* __restrict__ Y,
              const float* __restrict__ gamma, const float* __restrict__ beta,
              float* __restrict__ out, __half* __restrict__ outh)
{
    const int warp = (blockIdx.x * blockDim.x + threadIdx.x) >> 5;
    const int lane = threadIdx.x & 31;
    if (warp >= TTOK) return;

    const float* xr = X + (size_t)warp * DMODEL;
    const float* yr = Y + (size_t)warp * DMODEL;

    float v[16];
    float sum = 0.f;
    #pragma unroll
    for (int i = 0; i < 16; i++) {
        v[i] = xr[lane + i * 32] + yr[lane + i * 32];
        sum += v[i];
    }
    #pragma unroll
    for (int m = 16; m > 0; m >>= 1) sum += __shfl_xor_sync(0xffffffffu, sum, m);
    const float mu = sum * (1.f / DMODEL);

    float var = 0.f;
    #pragma unroll
    for (int i = 0; i < 16; i++) { const float d = v[i] - mu; var = fmaf(d, d, var); }
    #pragma unroll
    for (int m = 16; m > 0; m >>= 1) var += __shfl_xor_sync(0xffffffffu, var, m);
    const float rstd = rsqrtf(var * (1.f / DMODEL) + 1e-5f);

    float* orow = out + (size_t)warp * DMODEL;
    #pragma unroll
    for (int i = 0; i < 16; i++) {
        const int c = lane + i * 32;
        const float val = (v[i] - mu) * rstd * gamma[c] + beta[c];
        orow[c] = val;
        if (outh) outh[(size_t)warp * DMODEL + c] = __float2half_rn(val);
    }
}

// ---------------------------------------------------------------------------
// Launch orchestration
// ---------------------------------------------------------------------------
extern "C" void kernel_launch(void* const* d_in, const int* in_sizes, int n_in,
                              void* d_out, int out_size)
{
    const float* x     = (const float*)d_in[0];
    const float* Wq    = (const float*)d_in[1];
    const float* bq    = (const float*)d_in[2];
    const float* Wv    = (const float*)d_in[3];
    const float* bv    = (const float*)d_in[4];
    const float* Wr    = (const float*)d_in[5];
    const float* br    = (const float*)d_in[6];
    const float* W_h   = (const float*)d_in[7];
    const float* Wo    = (const float*)d_in[8];
    const float* bo    = (const float*)d_in[9];
    const float* ln1_g = (const float*)d_in[10];
    const float* ln1_b = (const float*)d_in[11];
    const float* Wf1   = (const float*)d_in[12];
    const float* bf1   = (const float*)d_in[13];
    const float* Wf2   = (const float*)d_in[14];
    const float* bf2   = (const float*)d_in[15];
    const float* ln2_g = (const float*)d_in[16];
    const float* ln2_b = (const float*)d_in[17];
    float* out = (float*)d_out;

    static __half *pxh = nullptr, *pQh, *pVh, *pRh, *pHh, *pAh, *px1h, *pFFh,
                  *pWqh, *pWvh, *pWrh, *pWoh, *pW1T, *pW2T;
    static float *pTmp, *pX1;
    if (!pxh) {
        cudaGetSymbolAddress((void**)&pxh,  g_xh);
        cudaGetSymbolAddress((void**)&pQh,  g_Qh);
        cudaGetSymbolAddress((void**)&pVh,  g_Vh);
        cudaGetSymbolAddress((void**)&pRh,  g_Rh);
        cudaGetSymbolAddress((void**)&pHh,  g_Hh);
        cudaGetSymbolAddress((void**)&pAh,  g_attnh);
        cudaGetSymbolAddress((void**)&px1h, g_x1h);
        cudaGetSymbolAddress((void**)&pFFh, g_ffh);
        cudaGetSymbolAddress((void**)&pWqh, g_Wqh);
        cudaGetSymbolAddress((void**)&pWvh, g_Wvh);
        cudaGetSymbolAddress((void**)&pWrh, g_Wrh);
        cudaGetSymbolAddress((void**)&pWoh, g_Woh);
        cudaGetSymbolAddress((void**)&pW1T, g_Wf1T);
        cudaGetSymbolAddress((void**)&pW2T, g_Wf2T);
        cudaGetSymbolAddress((void**)&pTmp, g_tmp);
        cudaGetSymbolAddress((void**)&pX1,  g_x1);
        cudaFuncSetAttribute(attn_h, cudaFuncAttributeMaxDynamicSharedMemorySize,
                             ATTN_SMEM);
        cudaFuncSetAttribute(gemm_h<false, true>,
                             cudaFuncAttributeMaxDynamicSharedMemorySize, GEMM_SMEM);
        cudaFuncSetAttribute(gemm_h<false, false>,
                             cudaFuncAttributeMaxDynamicSharedMemorySize, GEMM_SMEM);
        cudaFuncSetAttribute(gemm_h<true, true>,
                             cudaFuncAttributeMaxDynamicSharedMemorySize, GEMM_SMEM);
    }

    const dim3 gP (DMODEL / 128, TTOK / 128);   // (4, 128)
    const dim3 gF1(DFF    / 128, TTOK / 128);   // (16, 128)
    const dim3 gAt(SEQ / 128, BATCH * HEADS);   // (16, 64)
    const dim3 gLN(TTOK / 8, 1);

    // 0a) conversions needed for the projections
    f2h_kernel<<<(TTOK * DMODEL / 4 + 255) / 256, 256>>>(x, pxh, TTOK * DMODEL);
    f2h_kernel<<<(DMODEL * DMODEL / 4 + 255) / 256, 256>>>(Wq, pWqh, DMODEL * DMODEL);
    f2h_kernel<<<(DMODEL * DMODEL / 4 + 255) / 256, 256>>>(Wv, pWvh, DMODEL * DMODEL);
    f2h_kernel<<<(DMODEL * DMODEL / 4 + 255) / 256, 256>>>(Wr, pWrh, DMODEL * DMODEL);

    // 1) Q, V, R projections (ncu skip-5 lands on a GEMM)
    gemm_h<false, true><<<gP, 128, GEMM_SMEM>>>(pxh, pWqh, bq, pQh, TTOK, DMODEL, DMODEL);
    gemm_h<false, true><<<gP, 128, GEMM_SMEM>>>(pxh, pWvh, bv, pVh, TTOK, DMODEL, DMODEL);
    gemm_h<false, true><<<gP, 128, GEMM_SMEM>>>(pxh, pWrh, br, pRh, TTOK, DMODEL, DMODEL);

    // 2) recurrence -> keys H
    recur_kernel<<<16, 256>>>(pRh, W_h, pHh);

    // 3) attention (half in/out)
    attn_h<<<gAt, 128, ATTN_SMEM>>>(pQh, pHh, pVh, pAh);

    // 0b) deferred conversions (needed from step 4 onward)
    f2h_kernel<<<(DMODEL * DMODEL / 4 + 255) / 256, 256>>>(Wo, pWoh, DMODEL * DMODEL);
    transpose_h_kernel<<<dim3(DFF / 32, DMODEL / 32), 256>>>(Wf1, pW1T, DMODEL, DFF);
    transpose_h_kernel<<<dim3(DMODEL / 32, DFF / 32), 256>>>(Wf2, pW2T, DFF, DMODEL);

    // 4) output projection (fp32 out, feeds LN)
    gemm_h<false, false><<<gP, 128, GEMM_SMEM>>>(pAh, pWoh, bo, pTmp, TTOK, DMODEL, DMODEL);

    // 5) x1 = LN1(x + attn_proj): fp32 + half copies
    add_ln_kernel<<<gLN, 256>>>(x, pTmp, ln1_g, ln1_b, pX1, px1h);

    // 6) ff = relu(x1 @ Wf1 + bf1) (half out)
    gemm_h<true, true><<<gF1, 128, GEMM_SMEM>>>(px1h, pW1T, bf1, pFFh, TTOK, DFF, DMODEL);

    // 7) ff2 = ff @ Wf2 + bf2 (fp32 out, feeds LN)
    gemm_h<false, false><<<gP, 128, GEMM_SMEM>>>(pFFh, pW2T, bf2, pTmp, TTOK, DMODEL, DFF);

    // 8) out = LN2(x1 + ff2)
    add_ln_kernel<<<gLN, 256>>>(pX1, pTmp, ln2_g, ln2_b, out, nullptr);
}

// round 14
// speedup vs baseline: 1.2101x; 1.0542x over previous
#include <cuda_runtime.h>
#include <cuda_fp16.h>
#include <cstdint>

// ---------------------------------------------------------------------------
// Problem constants
// ---------------------------------------------------------------------------
#define SEQ    2048
#define BATCH  8
#define DMODEL 512
#define HEADS  8
#define DK     64
#define DFF    2048
#define TTOK   (SEQ * BATCH)          // 16384 tokens, t = s*BATCH + b

// ---------------------------------------------------------------------------
// Device scratch (static; cudaMalloc forbidden)
// ---------------------------------------------------------------------------
__device__ __half g_xh  [TTOK * DMODEL];
__device__ __half g_Qh  [TTOK * DMODEL];
__device__ __half g_Vh  [TTOK * DMODEL];
__device__ __half g_Rh  [TTOK * DMODEL];
__device__ __half g_Hh  [TTOK * DMODEL];
__device__ __half g_attnh[TTOK * DMODEL];
__device__ __half g_x1h [TTOK * DMODEL];
__device__ __half g_ffh [TTOK * DFF];
__device__ float  g_tmp [TTOK * DMODEL];
__device__ float  g_x1  [TTOK * DMODEL];
__device__ __half g_Wqh [DMODEL * DMODEL];
__device__ __half g_Wvh [DMODEL * DMODEL];
__device__ __half g_Wrh [DMODEL * DMODEL];
__device__ __half g_Woh [DMODEL * DMODEL];
__device__ __half g_Wf1T[DFF * DMODEL];   // [2048][512] half
__device__ __half g_Wf2T[DMODEL * DFF];   // [512][2048] half

// ---------------------------------------------------------------------------
// Helpers
// ---------------------------------------------------------------------------
__device__ __forceinline__ uint32_t smem_u32(const void* p) {
    uint32_t a;
    asm("{ .reg .u64 t; cvta.to.shared.u64 t, %1; cvt.u32.u64 %0, t; }"
        : "=r"(a) : "l"(p));
    return a;
}
__device__ __forceinline__ void cp16(uint32_t dst, const void* src) {
    asm volatile("cp.async.cg.shared.global [%0], [%1], 16;"
                 :: "r"(dst), "l"(src));
}
__device__ __forceinline__ void cp_commit() {
    asm volatile("cp.async.commit_group;" ::: "memory");
}
__device__ __forceinline__ void cp_wait1() {
    asm volatile("cp.async.wait_group 1;" ::: "memory");
}
__device__ __forceinline__ void cp_wait0() {
    asm volatile("cp.async.wait_group 0;" ::: "memory");
}
__device__ __forceinline__ void mma_f16(float c[4],
                                        uint32_t a0, uint32_t a1, uint32_t a2, uint32_t a3,
                                        uint32_t b0, uint32_t b1) {
    asm volatile(
        "mma.sync.aligned.m16n8k16.row.col.f32.f16.f16.f32 "
        "{%0,%1,%2,%3}, {%4,%5,%6,%7}, {%8,%9}, {%0,%1,%2,%3};\n"
        : "+f"(c[0]), "+f"(c[1]), "+f"(c[2]), "+f"(c[3])
        : "r"(a0), "r"(a1), "r"(a2), "r"(a3), "r"(b0), "r"(b1));
}
__device__ __forceinline__ void ldsm_x4(uint32_t& r0, uint32_t& r1,
                                        uint32_t& r2, uint32_t& r3, uint32_t addr) {
    asm volatile("ldmatrix.sync.aligned.m8n8.x4.shared.b16 {%0,%1,%2,%3}, [%4];"
                 : "=r"(r0), "=r"(r1), "=r"(r2), "=r"(r3) : "r"(addr));
}
__device__ __forceinline__ uint32_t ldh2(const __half* p) {
    return *(const uint32_t*)p;
}
__device__ __forceinline__ uint32_t ex2_f16x2(uint32_t h2) {
    uint32_t r;
    asm("ex2.approx.f16x2 %0, %1;" : "=r"(r) : "r"(h2));
    return r;
}

// ---------------------------------------------------------------------------
// fp16 GEMM (frozen from R11):
// C[M,N] = A[M,K] @ W^T + bias, A/W half, W is [N][K] row-major.
// Block 128x128, 128 threads (4 warps, 2x2), warp tile 64x64, BK=64.
// ---------------------------------------------------------------------------
#define GP        72                         // pitch in halfs (144 B)
#define G_AH      (128 * GP)                 // 9216 halfs per A tile
#define G_STAGEH  (2 * G_AH)                 // 18432 halfs (A + B)
#define GEMM_SMEM (3 * G_STAGEH * 2)         // 110592 B

template<bool RELU, bool OUTH>
__global__ void __launch_bounds__(128, 2)
gemm_h(const __half* __restrict__ A, const __half* __restrict__ W,
       const float* __restrict__ bias, void* __restrict__ Cout,
       int M, int N, int K)
{
    extern __shared__ __half sh[];
    const int tid  = threadIdx.x;
    const int warp = tid >> 5, lane = tid & 31;
    const int g = lane >> 2, t = lane & 3;
    const int bm = blockIdx.y * 128;
    const int bn = blockIdx.x * 128;
    const int wm = (warp >> 1) * 64;
    const int wn = (warp &  1) * 64;

    const uint32_t sbase = smem_u32(sh);

    float acc[4][8][4] = {};
    const int KT = K >> 6;   // k-tiles of 64 halfs

    auto fill = [&](int s, int kt) {
        const int k0 = kt << 6;
        const uint32_t st = sbase + (uint32_t)(s * G_STAGEH) * 2;
        #pragma unroll
        for (int i = 0; i < 8; i++) {
            const int idx = tid + i * 128;           // 0..1023
            const int r   = idx >> 3;                // 0..127
            const int kq  = (idx & 7) << 3;          // 0,8,...,56
            cp16(st + (uint32_t)(r * GP + kq) * 2,
                 A + (size_t)(bm + r) * K + k0 + kq);
            cp16(st + (uint32_t)(G_AH + r * GP + kq) * 2,
                 W + (size_t)(bn + r) * K + k0 + kq);
        }
        cp_commit();
    };

    fill(0, 0);
    fill(1, 1);

    for (int kt = 0; kt < KT; kt++) {
        if (kt + 1 < KT) cp_wait1(); else cp_wait0();
        __syncthreads();

        if (kt + 2 < KT) fill((kt + 2) % 3, kt + 2);

        const uint32_t sa = sbase + (uint32_t)((kt % 3) * G_STAGEH) * 2;
        const uint32_t sb = sa + (uint32_t)G_AH * 2;

        #pragma unroll
        for (int kk = 0; kk < 64; kk += 16) {
            uint32_t af[4][4], bf[8][2];
            #pragma unroll
            for (int mt = 0; mt < 4; mt++) {
                const uint32_t addr = sa +
                    (uint32_t)((wm + mt * 16 + (lane & 15)) * GP +
                               kk + (lane >> 4) * 8) * 2;
                ldsm_x4(af[mt][0], af[mt][1], af[mt][2], af[mt][3], addr);
            }
            #pragma unroll
            for (int np = 0; np < 4; np++) {
                const uint32_t addr = sb +
                    (uint32_t)((wn + np * 16 + (lane & 7) + ((lane >> 4) << 3)) * GP +
                               kk + ((lane >> 3) & 1) * 8) * 2;
                ldsm_x4(bf[2 * np][0], bf[2 * np][1],
                        bf[2 * np + 1][0], bf[2 * np + 1][1], addr);
            }
            #pragma unroll
            for (int mt = 0; mt < 4; mt++)
                #pragma unroll
                for (int nt = 0; nt < 8; nt++)
                    mma_f16(acc[mt][nt], af[mt][0], af[mt][1], af[mt][2], af[mt][3],
                            bf[nt][0], bf[nt][1]);
        }
        __syncthreads();
    }

    #pragma unroll
    for (int mt = 0; mt < 4; mt++) {
        const int r0 = bm + wm + mt * 16 + g;
        #pragma unroll
        for (int nt = 0; nt < 8; nt++) {
            const int c = bn + wn + nt * 8 + 2 * t;
            float v0 = acc[mt][nt][0] + bias[c];
            float v1 = acc[mt][nt][1] + bias[c + 1];
            float v2 = acc[mt][nt][2] + bias[c];
            float v3 = acc[mt][nt][3] + bias[c + 1];
            if (RELU) {
                v0 = fmaxf(v0, 0.f); v1 = fmaxf(v1, 0.f);
                v2 = fmaxf(v2, 0.f); v3 = fmaxf(v3, 0.f);
            }
            if (OUTH) {
                __half* C = (__half*)Cout;
                *(__half2*)&C[(size_t)r0 * N + c]       = __floats2half2_rn(v0, v1);
                *(__half2*)&C[(size_t)(r0 + 8) * N + c] = __floats2half2_rn(v2, v3);
            } else {
                float* C = (float*)Cout;
                *(float2*)&C[(size_t)r0 * N + c]       = make_float2(v0, v1);
                *(float2*)&C[(size_t)(r0 + 8) * N + c] = make_float2(v2, v3);
            }
        }
    }
}

// ---------------------------------------------------------------------------
// fp32 -> fp16 conversion (vectorized)
// ---------------------------------------------------------------------------
__global__ void __launch_bounds__(256)
f2h_kernel(const float* __restrict__ in, __half* __restrict__ out, int n)
{
    const int i = (blockIdx.x * blockDim.x + threadIdx.x) * 4;
    if (i < n) {
        float4 v = *(const float4*)(in + i);
        *(__half2*)(out + i)     = __floats2half2_rn(v.x, v.y);
        *(__half2*)(out + i + 2) = __floats2half2_rn(v.z, v.w);
    }
}

// ---------------------------------------------------------------------------
// Transpose + convert: out[c][r] = half(in[r][c]), in fp32 [R][Cc]
// ---------------------------------------------------------------------------
__global__ void __launch_bounds__(256)
transpose_h_kernel(const float* __restrict__ in, __half* __restrict__ out,
                   int R, int Cc)
{
    __shared__ float tile[32][33];
    const int c0 = blockIdx.x * 32, r0 = blockIdx.y * 32;
    const int tx = threadIdx.x & 31, ty = threadIdx.x >> 5;   // 32x8
    #pragma unroll
    for (int i = 0; i < 4; i++)
        tile[ty + i * 8][tx] = in[(size_t)(r0 + ty + i * 8) * Cc + c0 + tx];
    __syncthreads();
    #pragma unroll
    for (int i = 0; i < 4; i++)
        out[(size_t)(c0 + ty + i * 8) * R + r0 + tx] =
            __float2half_rn(tile[tx][ty + i * 8]);
}

// ---------------------------------------------------------------------------
// Recurrence: h_t = tanh(h_{t-1} * w_diag + r_t), lane-parallel, half I/O.
// ---------------------------------------------------------------------------
__global__ void recur_kernel(const __half* __restrict__ R,
                             const float* __restrict__ W_h,
                             __half* __restrict__ Hout)
{
    const int gid = blockIdx.x * blockDim.x + threadIdx.x;  // 0..4095
    if (gid >= BATCH * DMODEL) return;
    const int b  = gid >> 9;
    const int hn = gid & 511;

    float w = 0.f;
    const float* wrow = W_h + (size_t)hn * DK;
    #pragma unroll
    for (int k = 0; k < DK; k++) w += wrow[k];

    float hstate = 0.f;
    const size_t stride = (size_t)BATCH * DMODEL;
    size_t idx = (size_t)b * DMODEL + hn;
    #pragma unroll 8
    for (int s = 0; s < SEQ; s++) {
        const float r = __half2float(R[idx]);
        float x = fmaf(hstate, w, r);
        asm("tanh.approx.f32 %0, %1;" : "=f"(hstate) : "f"(x));
        Hout[idx] = __float2half_rn(hstate);
        idx += stride;
    }
}

// ---------------------------------------------------------------------------
// Flash attention (frozen from R13: register-pipelined K/V global loads,
// register-resident P, XOR-swizzled Vt).
// 4 warps, q-tile 128 (32 q/warp), key-tile 64.
// scores = (Q.K)*0.125 + (k>q ? 1.0 : 0.0)
// ---------------------------------------------------------------------------
#define AP       72
#define QS_OFF   0
#define KS_OFF   (128 * AP)
#define VT_OFF   (KS_OFF + 64 * AP)
#define ATTN_SMEM ((VT_OFF + 64 * AP) * 2)   // 36864 B
#define L2E      1.44269504089f

__global__ void __launch_bounds__(128)
attn_h(const __half* __restrict__ Q, const __half* __restrict__ Hk,
       const __half* __restrict__ V, __half* __restrict__ O)
{
    extern __shared__ __half sh[];
    __half (*Qs)[AP] = (__half(*)[AP])(sh + QS_OFF);
    __half (*Ks)[AP] = (__half(*)[AP])(sh + KS_OFF);
    __half (*Vt)[AP] = (__half(*)[AP])(sh + VT_OFF);

    const int tid  = threadIdx.x;
    const int warp = tid >> 5, lane = tid & 31;
    const int g = lane >> 2, t = lane & 3;
    const int bh = blockIdx.y;
    const int b  = bh >> 3, h = bh & 7;
    const int q0 = blockIdx.x << 7;          // 128 q rows per block

    // ---- stage Q tile (128 rows x 64 halfs) ----
    #pragma unroll
    for (int i = 0; i < 8; i++) {
        const int idx = tid + i * 128;       // 0..1023 8-half chunks
        const int r   = idx >> 3;            // 0..127
        const int dq  = (idx & 7) * 8;       // 0..56
        const size_t ga = ((size_t)(q0 + r) * BATCH + b) * DMODEL + h * DK + dq;
        *(float4*)&Qs[r][dq] = *(const float4*)&Q[ga];
    }

    float o[2][8][4] = {};
    float mrow[4] = {-1e30f, -1e30f, -1e30f, -1e30f};
    float lrow[4] = {0.f, 0.f, 0.f, 0.f};
    const float scale = 0.125f;

    float4 kreg[4], vreg[4];
    auto load_tile = [&](int k0) {
        #pragma unroll
        for (int i = 0; i < 4; i++) {
            const int idx = tid + i * 128;
            const int r   = idx >> 3;
            const int dq  = (idx & 7) * 8;
            const size_t ga = ((size_t)(k0 + r) * BATCH + b) * DMODEL + h * DK + dq;
            kreg[i] = *(const float4*)&Hk[ga];
            vreg[i] = *(const float4*)&V[ga];
        }
    };

    load_tile(0);
    __syncthreads();   // Qs visible

    for (int k0 = 0; k0 < SEQ; k0 += 64) {
        // ---- store staged K/V registers to smem ----
        #pragma unroll
        for (int i = 0; i < 4; i++) {
            const int idx = tid + i * 128;
            const int r   = idx >> 3;
            const int dq  = (idx & 7) * 8;
            *(float4*)&Ks[r][dq] = kreg[i];
            const __half* vp = (const __half*)&vreg[i];
            #pragma unroll
            for (int j = 0; j < 8; j++)
                Vt[dq + j][r ^ dq] = vp[j];   // (dq+j)&56 == dq for j<8
        }
        __syncthreads();

        // ---- prefetch next tile into registers (overlaps compute below) ----
        if (k0 + 64 < SEQ) load_tile(k0 + 64);

        #pragma unroll
        for (int mt = 0; mt < 2; mt++) {
            const int qrow = warp * 32 + mt * 16;

            // ---- S = Q @ K^T  (16q x 64k, d=64 in 4 k16 steps) ----
            float s[8][4] = {};
            #pragma unroll
            for (int kk = 0; kk < 64; kk += 16) {
                const uint32_t a0 = ldh2(&Qs[qrow + g    ][kk + 2 * t    ]);
                const uint32_t a1 = ldh2(&Qs[qrow + 8 + g][kk + 2 * t    ]);
                const uint32_t a2 = ldh2(&Qs[qrow + g    ][kk + 2 * t + 8]);
                const uint32_t a3 = ldh2(&Qs[qrow + 8 + g][kk + 2 * t + 8]);
                #pragma unroll
                for (int nt = 0; nt < 8; nt++) {
                    const uint32_t b0 = ldh2(&Ks[nt * 8 + g][kk + 2 * t    ]);
                    const uint32_t b1 = ldh2(&Ks[nt * 8 + g][kk + 2 * t + 8]);
                    mma_f16(s[nt], a0, a1, a2, a3, b0, b1);
                }
            }

            // ---- scale + mask ----
            const int qg0 = q0 + qrow + g;
            #pragma unroll
            for (int nt = 0; nt < 8; nt++) {
                const int kg = k0 + nt * 8 + 2 * t;
                s[nt][0] = s[nt][0] * scale + ((kg     > qg0    ) ? 1.f : 0.f);
                s[nt][1] = s[nt][1] * scale + ((kg + 1 > qg0    ) ? 1.f : 0.f);
                s[nt][2] = s[nt][2] * scale + ((kg     > qg0 + 8) ? 1.f : 0.f);
                s[nt][3] = s[nt][3] * scale + ((kg + 1 > qg0 + 8) ? 1.f : 0.f);
            }

            // ---- online softmax (rows g, g+8), packed f16x2 ex2 ----
            uint32_t p2[8][2];   // exp results as half2 == PV A-fragments
            #pragma unroll
            for (int half_i = 0; half_i < 2; half_i++) {
                const int ri = mt * 2 + half_i;
                float tm = -1e30f;
                #pragma unroll
                for (int nt = 0; nt < 8; nt++) {
                    tm = fmaxf(tm, s[nt][2 * half_i]);
                    tm = fmaxf(tm, s[nt][2 * half_i + 1]);
                }
                tm = fmaxf(tm, __shfl_xor_sync(0xffffffffu, tm, 1));
                tm = fmaxf(tm, __shfl_xor_sync(0xffffffffu, tm, 2));
                const float mnew = fmaxf(mrow[ri], tm);
                const float corr = __expf(mrow[ri] - mnew);
                const float mnL  = mnew * L2E;
                float ts = 0.f;
                #pragma unroll
                for (int nt = 0; nt < 8; nt++) {
                    const float a0 = fmaf(s[nt][2 * half_i],     L2E, -mnL);
                    const float a1 = fmaf(s[nt][2 * half_i + 1], L2E, -mnL);
                    __half2 hh = __floats2half2_rn(a0, a1);
                    const uint32_t pe = ex2_f16x2(*(uint32_t*)&hh);
                    p2[nt][half_i] = pe;
                    const float2 f = __half22float2(*(__half2*)&pe);
                    ts += f.x + f.y;
                }
                ts += __shfl_xor_sync(0xffffffffu, ts, 1);
                ts += __shfl_xor_sync(0xffffffffu, ts, 2);
                lrow[ri] = lrow[ri] * corr + ts;
                mrow[ri] = mnew;
                #pragma unroll
                for (int nt = 0; nt < 8; nt++) {
                    o[mt][nt][2 * half_i]     *= corr;
                    o[mt][nt][2 * half_i + 1] *= corr;
                }
            }

            // ---- O += P @ V : p2 used directly as A-fragments ----
            #pragma unroll
            for (int j = 0; j < 4; j++) {
                const uint32_t a0 = p2[2 * j][0];
                const uint32_t a1 = p2[2 * j][1];
                const uint32_t a2 = p2[2 * j + 1][0];
                const uint32_t a3 = p2[2 * j + 1][1];
                #pragma unroll
                for (int nt = 0; nt < 8; nt++) {
                    const int row = nt * 8 + g;
                    const int sw  = nt * 8;           // row & 56 (g < 8)
                    const uint32_t b0 = ldh2(&Vt[row][(j * 16 + 2 * t    ) ^ sw]);
                    const uint32_t b1 = ldh2(&Vt[row][(j * 16 + 2 * t + 8) ^ sw]);
                    mma_f16(o[mt][nt], a0, a1, a2, a3, b0, b1);
                }
            }
        }
        __syncthreads();   // protect Ks/Vt for next tile's store phase
    }

    // ---- epilogue: normalize & store half ----
    #pragma unroll
    for (int mt = 0; mt < 2; mt++) {
        const float inv0 = 1.f / lrow[mt * 2];
        const float inv1 = 1.f / lrow[mt * 2 + 1];
        const int r0 = q0 + warp * 32 + mt * 16 + g;
        #pragma unroll
        for (int nt = 0; nt < 8; nt++) {
            const int c = h * DK + nt * 8 + 2 * t;
            *(__half2*)&O[((size_t)r0 * BATCH + b) * DMODEL + c] =
                __floats2half2_rn(o[mt][nt][0] * inv0, o[mt][nt][1] * inv0);
            *(__half2*)&O[((size_t)(r0 + 8) * BATCH + b) * DMODEL + c] =
                __floats2half2_rn(o[mt][nt][2] * inv1, o[mt][nt][3] * inv1);
        }
    }
}

// ---------------------------------------------------------------------------
// Fused residual-add + LayerNorm; optional half copy of the output.
// ---------------------------------------------------------------------------
__global__ void __launch_bounds__(256)
add_ln_kernel(const float* __restrict__ X, const float* __restrict__ Y,
              const float* __restrict__ gamma, const float* __restrict__ beta,
              float* __restrict__ out, __half* __restrict__ outh)
{
    const int warp = (blockIdx.x * blockDim.x + threadIdx.x) >> 5;
    const int lane = threadIdx.x & 31;
    if (warp >= TTOK) return;

    const float* xr = X + (size_t)warp * DMODEL;
    const float* yr = Y + (size_t)warp * DMODEL;

    float v[16];
    float sum = 0.f;
    #pragma unroll
    for (int i = 0; i < 16; i++) {
        v[i] = xr[lane + i * 32] + yr[lane + i * 32];
        sum += v[i];
    }
    #pragma unroll
    for (int m = 16; m > 0; m >>= 1) sum += __shfl_xor_sync(0xffffffffu, sum, m);
    const float mu = sum * (1.f / DMODEL);

    float var = 0.f;
    #pragma unroll
    for (int i = 0; i < 16; i++) { const float d = v[i] - mu; var = fmaf(d, d, var); }
    #pragma unroll
    for (int m = 16; m > 0; m >>= 1) var += __shfl_xor_sync(0xffffffffu, var, m);
    const float rstd = rsqrtf(var * (1.f / DMODEL) + 1e-5f);

    float* orow = out + (size_t)warp * DMODEL;
    #pragma unroll
    for (int i = 0; i < 16; i++) {
        const int c = lane + i * 32;
        const float val = (v[i] - mu) * rstd * gamma[c] + beta[c];
        orow[c] = val;
        if (outh) outh[(size_t)warp * DMODEL + c] = __float2half_rn(val);
    }
}

// ---------------------------------------------------------------------------
// Launch orchestration: graph fork/join via side streams.
//   branch s1: gemm R -> recur          (overlaps Q/V projections)
//   branch s2: f2h(Wo), FF transposes   (overlaps projections + attention)
// ---------------------------------------------------------------------------
extern "C" void kernel_launch(void* const* d_in, const int* in_sizes, int n_in,
                              void* d_out, int out_size)
{
    const float* x     = (const float*)d_in[0];
    const float* Wq    = (const float*)d_in[1];
    const float* bq    = (const float*)d_in[2];
    const float* Wv    = (const float*)d_in[3];
    const float* bv    = (const float*)d_in[4];
    const float* Wr    = (const float*)d_in[5];
    const float* br    = (const float*)d_in[6];
    const float* W_h   = (const float*)d_in[7];
    const float* Wo    = (const float*)d_in[8];
    const float* bo    = (const float*)d_in[9];
    const float* ln1_g = (const float*)d_in[10];
    const float* ln1_b = (const float*)d_in[11];
    const float* Wf1   = (const float*)d_in[12];
    const float* bf1   = (const float*)d_in[13];
    const float* Wf2   = (const float*)d_in[14];
    const float* bf2   = (const float*)d_in[15];
    const float* ln2_g = (const float*)d_in[16];
    const float* ln2_b = (const float*)d_in[17];
    float* out = (float*)d_out;

    static __half *pxh = nullptr, *pQh, *pVh, *pRh, *pHh, *pAh, *px1h, *pFFh,
                  *pWqh, *pWvh, *pWrh, *pWoh, *pW1T, *pW2T;
    static float *pTmp, *pX1;
    static cudaStream_t s1, s2;
    static cudaEvent_t evRoot, evH, evW;
    if (!pxh) {
        cudaGetSymbolAddress((void**)&pxh,  g_xh);
        cudaGetSymbolAddress((void**)&pQh,  g_Qh);
        cudaGetSymbolAddress((void**)&pVh,  g_Vh);
        cudaGetSymbolAddress((void**)&pRh,  g_Rh);
        cudaGetSymbolAddress((void**)&pHh,  g_Hh);
        cudaGetSymbolAddress((void**)&pAh,  g_attnh);
        cudaGetSymbolAddress((void**)&px1h, g_x1h);
        cudaGetSymbolAddress((void**)&pFFh, g_ffh);
        cudaGetSymbolAddress((void**)&pWqh, g_Wqh);
        cudaGetSymbolAddress((void**)&pWvh, g_Wvh);
        cudaGetSymbolAddress((void**)&pWrh, g_Wrh);
        cudaGetSymbolAddress((void**)&pWoh, g_Woh);
        cudaGetSymbolAddress((void**)&pW1T, g_Wf1T);
        cudaGetSymbolAddress((void**)&pW2T, g_Wf2T);
        cudaGetSymbolAddress((void**)&pTmp, g_tmp);
        cudaGetSymbolAddress((void**)&pX1,  g_x1);
        cudaFuncSetAttribute(attn_h, cudaFuncAttributeMaxDynamicSharedMemorySize,
                             ATTN_SMEM);
        cudaFuncSetAttribute(gemm_h<false, true>,
                             cudaFuncAttributeMaxDynamicSharedMemorySize, GEMM_SMEM);
        cudaFuncSetAttribute(gemm_h<false, false>,
                             cudaFuncAttributeMaxDynamicSharedMemorySize, GEMM_SMEM);
        cudaFuncSetAttribute(gemm_h<true, true>,
                             cudaFuncAttributeMaxDynamicSharedMemorySize, GEMM_SMEM);
        cudaStreamCreateWithFlags(&s1, cudaStreamNonBlocking);
        cudaStreamCreateWithFlags(&s2, cudaStreamNonBlocking);
        cudaEventCreateWithFlags(&evRoot, cudaEventDisableTiming);
        cudaEventCreateWithFlags(&evH,    cudaEventDisableTiming);
        cudaEventCreateWithFlags(&evW,    cudaEventDisableTiming);
    }

    const dim3 gP (DMODEL / 128, TTOK / 128);   // (4, 128)
    const dim3 gF1(DFF    / 128, TTOK / 128);   // (16, 128)
    const dim3 gAt(SEQ / 128, BATCH * HEADS);   // (16, 64)
    const dim3 gLN(TTOK / 8, 1);

    // ---- root: conversions needed for R branch + fork point ----
    f2h_kernel<<<(TTOK * DMODEL / 4 + 255) / 256, 256>>>(x, pxh, TTOK * DMODEL);
    f2h_kernel<<<(DMODEL * DMODEL / 4 + 255) / 256, 256>>>(Wr, pWrh, DMODEL * DMODEL);
    cudaEventRecord(evRoot, 0);

    // ---- branch s1: R projection + recurrence -> H ----
    cudaStreamWaitEvent(s1, evRoot, 0);
    gemm_h<false, true><<<gP, 128, GEMM_SMEM, s1>>>(pxh, pWrh, br, pRh,
                                                    TTOK, DMODEL, DMODEL);
    recur_kernel<<<16, 256, 0, s1>>>(pRh, W_h, pHh);
    cudaEventRecord(evH, s1);

    // ---- branch s2: deferred weight conversions ----
    cudaStreamWaitEvent(s2, evRoot, 0);
    f2h_kernel<<<(DMODEL * DMODEL / 4 + 255) / 256, 256, 0, s2>>>(
        Wo, pWoh, DMODEL * DMODEL);
    transpose_h_kernel<<<dim3(DFF / 32, DMODEL / 32), 256, 0, s2>>>(
        Wf1, pW1T, DMODEL, DFF);
    transpose_h_kernel<<<dim3(DMODEL / 32, DFF / 32), 256, 0, s2>>>(
        Wf2, pW2T, DFF, DMODEL);
    cudaEventRecord(evW, s2);

    // ---- main: Q, V projections (concurrent with s1/s2) ----
    f2h_kernel<<<(DMODEL * DMODEL / 4 + 255) / 256, 256>>>(Wq, pWqh, DMODEL * DMODEL);
    f2h_kernel<<<(DMODEL * DMODEL / 4 + 255) / 256, 256>>>(Wv, pWvh, DMODEL * DMODEL);
    gemm_h<false, true><<<gP, 128, GEMM_SMEM>>>(pxh, pWqh, bq, pQh, TTOK, DMODEL, DMODEL);
    gemm_h<false, true><<<gP, 128, GEMM_SMEM>>>(pxh, pWvh, bv, pVh, TTOK, DMODEL, DMODEL);

    // ---- join H, run attention ----
    cudaStreamWaitEvent(0, evH, 0);
    attn_h<<<gAt, 128, ATTN_SMEM>>>(pQh, pHh, pVh, pAh);

    // ---- join weight branch, then the tail chain ----
    cudaStreamWaitEvent(0, evW, 0);
    gemm_h<false, false><<<gP, 128, GEMM_SMEM>>>(pAh, pWoh, bo, pTmp, TTOK, DMODEL, DMODEL);
    add_ln_kernel<<<gLN, 256>>>(x, pTmp, ln1_g, ln1_b, pX1, px1h);
    gemm_h<true, true><<<gF1, 128, GEMM_SMEM>>>(px1h, pW1T, bf1, pFFh, TTOK, DFF, DMODEL);
    gemm_h<false, false><<<gP, 128, GEMM_SMEM>>>(pFFh, pW2T, bf2, pTmp, TTOK, DMODEL, DFF);
    add_ln_kernel<<<gLN, 256>>>(pX1, pTmp, ln2_g, ln2_b, out, nullptr);
}

// round 15
// speedup vs baseline: 1.2944x; 1.0696x over previous
#include <cuda_runtime.h>
#include <cuda_fp16.h>
#include <cstdint>

// ---------------------------------------------------------------------------
// Problem constants
// ---------------------------------------------------------------------------
#define SEQ    2048
#define BATCH  8
#define DMODEL 512
#define HEADS  8
#define DK     64
#define DFF    2048
#define TTOK   (SEQ * BATCH)          // 16384 tokens, t = s*BATCH + b

// ---------------------------------------------------------------------------
// Device scratch (static; cudaMalloc forbidden)
// ---------------------------------------------------------------------------
__device__ __half g_xh  [TTOK * DMODEL];
__device__ __half g_Qh  [TTOK * DMODEL];
__device__ __half g_Vh  [TTOK * DMODEL];
__device__ __half g_Rh  [TTOK * DMODEL];
__device__ __half g_Hh  [TTOK * DMODEL];
__device__ __half g_attnh[TTOK * DMODEL];
__device__ __half g_x1h [TTOK * DMODEL];
__device__ __half g_ffh [TTOK * DFF];
__device__ float  g_tmp [TTOK * DMODEL];
__device__ float  g_x1  [TTOK * DMODEL];
__device__ __half g_Wqh [DMODEL * DMODEL];
__device__ __half g_Wvh [DMODEL * DMODEL];
__device__ __half g_Wrh [DMODEL * DMODEL];
__device__ __half g_Woh [DMODEL * DMODEL];
__device__ __half g_Wf1T[DFF * DMODEL];   // [2048][512] half
__device__ __half g_Wf2T[DMODEL * DFF];   // [512][2048] half

// ---------------------------------------------------------------------------
// Helpers
// ---------------------------------------------------------------------------
__device__ __forceinline__ uint32_t smem_u32(const void* p) {
    uint32_t a;
    asm("{ .reg .u64 t; cvta.to.shared.u64 t, %1; cvt.u32.u64 %0, t; }"
        : "=r"(a) : "l"(p));
    return a;
}
__device__ __forceinline__ void cp16(uint32_t dst, const void* src) {
    asm volatile("cp.async.cg.shared.global [%0], [%1], 16;"
                 :: "r"(dst), "l"(src));
}
__device__ __forceinline__ void cp_commit() {
    asm volatile("cp.async.commit_group;" ::: "memory");
}
__device__ __forceinline__ void cp_wait1() {
    asm volatile("cp.async.wait_group 1;" ::: "memory");
}
__device__ __forceinline__ void cp_wait0() {
    asm volatile("cp.async.wait_group 0;" ::: "memory");
}
__device__ __forceinline__ void mma_f16(float c[4],
                                        uint32_t a0, uint32_t a1, uint32_t a2, uint32_t a3,
                                        uint32_t b0, uint32_t b1) {
    asm volatile(
        "mma.sync.aligned.m16n8k16.row.col.f32.f16.f16.f32 "
        "{%0,%1,%2,%3}, {%4,%5,%6,%7}, {%8,%9}, {%0,%1,%2,%3};\n"
        : "+f"(c[0]), "+f"(c[1]), "+f"(c[2]), "+f"(c[3])
        : "r"(a0), "r"(a1), "r"(a2), "r"(a3), "r"(b0), "r"(b1));
}
__device__ __forceinline__ void ldsm_x4(uint32_t& r0, uint32_t& r1,
                                        uint32_t& r2, uint32_t& r3, uint32_t addr) {
    asm volatile("ldmatrix.sync.aligned.m8n8.x4.shared.b16 {%0,%1,%2,%3}, [%4];"
                 : "=r"(r0), "=r"(r1), "=r"(r2), "=r"(r3) : "r"(addr));
}
__device__ __forceinline__ uint32_t ldh2(const __half* p) {
    return *(const uint32_t*)p;
}
__device__ __forceinline__ uint32_t ex2_f16x2(uint32_t h2) {
    uint32_t r;
    asm("ex2.approx.f16x2 %0, %1;" : "=r"(r) : "r"(h2));
    return r;
}

// ---------------------------------------------------------------------------
// fp16 GEMM (frozen from R11):
// C[M,N] = A[M,K] @ W^T + bias, A/W half, W is [N][K] row-major.
// Block 128x128, 128 threads (4 warps, 2x2), warp tile 64x64, BK=64.
// ---------------------------------------------------------------------------
#define GP        72                         // pitch in halfs (144 B)
#define G_AH      (128 * GP)                 // 9216 halfs per A tile
#define G_STAGEH  (2 * G_AH)                 // 18432 halfs (A + B)
#define GEMM_SMEM (3 * G_STAGEH * 2)         // 110592 B

template<bool RELU, bool OUTH>
__global__ void __launch_bounds__(128, 2)
gemm_h(const __half* __restrict__ A, const __half* __restrict__ W,
       const float* __restrict__ bias, void* __restrict__ Cout,
       int M, int N, int K)
{
    extern __shared__ __half sh[];
    const int tid  = threadIdx.x;
    const int warp = tid >> 5, lane = tid & 31;
    const int g = lane >> 2, t = lane & 3;
    const int bm = blockIdx.y * 128;
    const int bn = blockIdx.x * 128;
    const int wm = (warp >> 1) * 64;
    const int wn = (warp &  1) * 64;

    const uint32_t sbase = smem_u32(sh);

    float acc[4][8][4] = {};
    const int KT = K >> 6;   // k-tiles of 64 halfs

    auto fill = [&](int s, int kt) {
        const int k0 = kt << 6;
        const uint32_t st = sbase + (uint32_t)(s * G_STAGEH) * 2;
        #pragma unroll
        for (int i = 0; i < 8; i++) {
            const int idx = tid + i * 128;           // 0..1023
            const int r   = idx >> 3;                // 0..127
            const int kq  = (idx & 7) << 3;          // 0,8,...,56
            cp16(st + (uint32_t)(r * GP + kq) * 2,
                 A + (size_t)(bm + r) * K + k0 + kq);
            cp16(st + (uint32_t)(G_AH + r * GP + kq) * 2,
                 W + (size_t)(bn + r) * K + k0 + kq);
        }
        cp_commit();
    };

    fill(0, 0);
    fill(1, 1);

    for (int kt = 0; kt < KT; kt++) {
        if (kt + 1 < KT) cp_wait1(); else cp_wait0();
        __syncthreads();

        if (kt + 2 < KT) fill((kt + 2) % 3, kt + 2);

        const uint32_t sa = sbase + (uint32_t)((kt % 3) * G_STAGEH) * 2;
        const uint32_t sb = sa + (uint32_t)G_AH * 2;

        #pragma unroll
        for (int kk = 0; kk < 64; kk += 16) {
            uint32_t af[4][4], bf[8][2];
            #pragma unroll
            for (int mt = 0; mt < 4; mt++) {
                const uint32_t addr = sa +
                    (uint32_t)((wm + mt * 16 + (lane & 15)) * GP +
                               kk + (lane >> 4) * 8) * 2;
                ldsm_x4(af[mt][0], af[mt][1], af[mt][2], af[mt][3], addr);
            }
            #pragma unroll
            for (int np = 0; np < 4; np++) {
                const uint32_t addr = sb +
                    (uint32_t)((wn + np * 16 + (lane & 7) + ((lane >> 4) << 3)) * GP +
                               kk + ((lane >> 3) & 1) * 8) * 2;
                ldsm_x4(bf[2 * np][0], bf[2 * np][1],
                        bf[2 * np + 1][0], bf[2 * np + 1][1], addr);
            }
            #pragma unroll
            for (int mt = 0; mt < 4; mt++)
                #pragma unroll
                for (int nt = 0; nt < 8; nt++)
                    mma_f16(acc[mt][nt], af[mt][0], af[mt][1], af[mt][2], af[mt][3],
                            bf[nt][0], bf[nt][1]);
        }
        __syncthreads();
    }

    #pragma unroll
    for (int mt = 0; mt < 4; mt++) {
        const int r0 = bm + wm + mt * 16 + g;
        #pragma unroll
        for (int nt = 0; nt < 8; nt++) {
            const int c = bn + wn + nt * 8 + 2 * t;
            float v0 = acc[mt][nt][0] + bias[c];
            float v1 = acc[mt][nt][1] + bias[c + 1];
            float v2 = acc[mt][nt][2] + bias[c];
            float v3 = acc[mt][nt][3] + bias[c + 1];
            if (RELU) {
                v0 = fmaxf(v0, 0.f); v1 = fmaxf(v1, 0.f);
                v2 = fmaxf(v2, 0.f); v3 = fmaxf(v3, 0.f);
            }
            if (OUTH) {
                __half* C = (__half*)Cout;
                *(__half2*)&C[(size_t)r0 * N + c]       = __floats2half2_rn(v0, v1);
                *(__half2*)&C[(size_t)(r0 + 8) * N + c] = __floats2half2_rn(v2, v3);
            } else {
                float* C = (float*)Cout;
                *(float2*)&C[(size_t)r0 * N + c]       = make_float2(v0, v1);
                *(float2*)&C[(size_t)(r0 + 8) * N + c] = make_float2(v2, v3);
            }
        }
    }
}

// ---------------------------------------------------------------------------
// fp32 -> fp16 conversion (vectorized)
// ---------------------------------------------------------------------------
__global__ void __launch_bounds__(256)
f2h_kernel(const float* __restrict__ in, __half* __restrict__ out, int n)
{
    const int i = (blockIdx.x * blockDim.x + threadIdx.x) * 4;
    if (i < n) {
        float4 v = *(const float4*)(in + i);
        *(__half2*)(out + i)     = __floats2half2_rn(v.x, v.y);
        *(__half2*)(out + i + 2) = __floats2half2_rn(v.z, v.w);
    }
}

// ---------------------------------------------------------------------------
// Transpose + convert: out[c][r] = half(in[r][c]), in fp32 [R][Cc]
// ---------------------------------------------------------------------------
__global__ void __launch_bounds__(256)
transpose_h_kernel(const float* __restrict__ in, __half* __restrict__ out,
                   int R, int Cc)
{
    __shared__ float tile[32][33];
    const int c0 = blockIdx.x * 32, r0 = blockIdx.y * 32;
    const int tx = threadIdx.x & 31, ty = threadIdx.x >> 5;   // 32x8
    #pragma unroll
    for (int i = 0; i < 4; i++)
        tile[ty + i * 8][tx] = in[(size_t)(r0 + ty + i * 8) * Cc + c0 + tx];
    __syncthreads();
    #pragma unroll
    for (int i = 0; i < 4; i++)
        out[(size_t)(c0 + ty + i * 8) * R + r0 + tx] =
            __float2half_rn(tile[tx][ty + i * 8]);
}

// ---------------------------------------------------------------------------
// Recurrence v2: h_t = tanh(h_{t-1} * w_diag + r_t), lane-parallel.
// Depth-8 explicit register prefetch: load for step s+8 issues as soon as
// rv[i] is consumed -> 8 loads in flight, L2 latency amortized under the
// fma+tanh chain. Grid 32x128 (1 warp/SMSP: MUFU rt-8 < 20-cyc chain).
// ---------------------------------------------------------------------------
__global__ void __launch_bounds__(128)
recur_kernel(const __half* __restrict__ R,
             const float* __restrict__ W_h,
             __half* __restrict__ Hout)
{
    const int gid = blockIdx.x * blockDim.x + threadIdx.x;  // 0..4095
    if (gid >= BATCH * DMODEL) return;
    const int b  = gid >> 9;
    const int hn = gid & 511;

    float w = 0.f;
    const float* wrow = W_h + (size_t)hn * DK;
    #pragma unroll
    for (int k = 0; k < DK; k++) w += wrow[k];

    const size_t stride = (size_t)BATCH * DMODEL;   // 4096
    const size_t base   = (size_t)b * DMODEL + hn;

    float hstate = 0.f;
    float rv[8];
    #pragma unroll
    for (int i = 0; i < 8; i++)
        rv[i] = __half2float(R[base + (size_t)i * stride]);

    size_t widx = base;                 // write index (step s)
    size_t pidx = base + 8 * stride;    // prefetch index (step s+8)

    // main loop: 2040 steps with prefetch
    for (int s8 = 0; s8 < SEQ / 8 - 1; s8++) {
        #pragma unroll
        for (int i = 0; i < 8; i++) {
            const float x = fmaf(hstate, w, rv[i]);
            asm("tanh.approx.f32 %0, %1;" : "=f"(hstate) : "f"(x));
            Hout[widx] = __float2half_rn(hstate);
            rv[i] = __half2float(R[pidx]);     // prefetch step s+8
            widx += stride;
            pidx += stride;
        }
    }
    // tail: last 8 steps, no prefetch
    #pragma unroll
    for (int i = 0; i < 8; i++) {
        const float x = fmaf(hstate, w, rv[i]);
        asm("tanh.approx.f32 %0, %1;" : "=f"(hstate) : "f"(x));
        Hout[widx] = __float2half_rn(hstate);
        widx += stride;
    }
}

// ---------------------------------------------------------------------------
// Flash attention (frozen from R13: register-pipelined K/V global loads,
// register-resident P, XOR-swizzled Vt).
// 4 warps, q-tile 128 (32 q/warp), key-tile 64.
// scores = (Q.K)*0.125 + (k>q ? 1.0 : 0.0)
// ---------------------------------------------------------------------------
#define AP       72
#define QS_OFF   0
#define KS_OFF   (128 * AP)
#define VT_OFF   (KS_OFF + 64 * AP)
#define ATTN_SMEM ((VT_OFF + 64 * AP) * 2)   // 36864 B
#define L2E      1.44269504089f

__global__ void __launch_bounds__(128)
attn_h(const __half* __restrict__ Q, const __half* __restrict__ Hk,
       const __half* __restrict__ V, __half* __restrict__ O)
{
    extern __shared__ __half sh[];
    __half (*Qs)[AP] = (__half(*)[AP])(sh + QS_OFF);
    __half (*Ks)[AP] = (__half(*)[AP])(sh + KS_OFF);
    __half (*Vt)[AP] = (__half(*)[AP])(sh + VT_OFF);

    const int tid  = threadIdx.x;
    const int warp = tid >> 5, lane = tid & 31;
    const int g = lane >> 2, t = lane & 3;
    const int bh = blockIdx.y;
    const int b  = bh >> 3, h = bh & 7;
    const int q0 = blockIdx.x << 7;          // 128 q rows per block

    // ---- stage Q tile (128 rows x 64 halfs) ----
    #pragma unroll
    for (int i = 0; i < 8; i++) {
        const int idx = tid + i * 128;       // 0..1023 8-half chunks
        const int r   = idx >> 3;            // 0..127
        const int dq  = (idx & 7) * 8;       // 0..56
        const size_t ga = ((size_t)(q0 + r) * BATCH + b) * DMODEL + h * DK + dq;
        *(float4*)&Qs[r][dq] = *(const float4*)&Q[ga];
    }

    float o[2][8][4] = {};
    float mrow[4] = {-1e30f, -1e30f, -1e30f, -1e30f};
    float lrow[4] = {0.f, 0.f, 0.f, 0.f};
    const float scale = 0.125f;

    float4 kreg[4], vreg[4];
    auto load_tile = [&](int k0) {
        #pragma unroll
        for (int i = 0; i < 4; i++) {
            const int idx = tid + i * 128;
            const int r   = idx >> 3;
            const int dq  = (idx & 7) * 8;
            const size_t ga = ((size_t)(k0 + r) * BATCH + b) * DMODEL + h * DK + dq;
            kreg[i] = *(const float4*)&Hk[ga];
            vreg[i] = *(const float4*)&V[ga];
        }
    };

    load_tile(0);
    __syncthreads();   // Qs visible

    for (int k0 = 0; k0 < SEQ; k0 += 64) {
        // ---- store staged K/V registers to smem ----
        #pragma unroll
        for (int i = 0; i < 4; i++) {
            const int idx = tid + i * 128;
            const int r   = idx >> 3;
            const int dq  = (idx & 7) * 8;
            *(float4*)&Ks[r][dq] = kreg[i];
            const __half* vp = (const __half*)&vreg[i];
            #pragma unroll
            for (int j = 0; j < 8; j++)
                Vt[dq + j][r ^ dq] = vp[j];   // (dq+j)&56 == dq for j<8
        }
        __syncthreads();

        // ---- prefetch next tile into registers (overlaps compute below) ----
        if (k0 + 64 < SEQ) load_tile(k0 + 64);

        #pragma unroll
        for (int mt = 0; mt < 2; mt++) {
            const int qrow = warp * 32 + mt * 16;

            // ---- S = Q @ K^T  (16q x 64k, d=64 in 4 k16 steps) ----
            float s[8][4] = {};
            #pragma unroll
            for (int kk = 0; kk < 64; kk += 16) {
                const uint32_t a0 = ldh2(&Qs[qrow + g    ][kk + 2 * t    ]);
                const uint32_t a1 = ldh2(&Qs[qrow + 8 + g][kk + 2 * t    ]);
                const uint32_t a2 = ldh2(&Qs[qrow + g    ][kk + 2 * t + 8]);
                const uint32_t a3 = ldh2(&Qs[qrow + 8 + g][kk + 2 * t + 8]);
                #pragma unroll
                for (int nt = 0; nt < 8; nt++) {
                    const uint32_t b0 = ldh2(&Ks[nt * 8 + g][kk + 2 * t    ]);
                    const uint32_t b1 = ldh2(&Ks[nt * 8 + g][kk + 2 * t + 8]);
                    mma_f16(s[nt], a0, a1, a2, a3, b0, b1);
                }
            }

            // ---- scale + mask ----
            const int qg0 = q0 + qrow + g;
            #pragma unroll
            for (int nt = 0; nt < 8; nt++) {
                const int kg = k0 + nt * 8 + 2 * t;
                s[nt][0] = s[nt][0] * scale + ((kg     > qg0    ) ? 1.f : 0.f);
                s[nt][1] = s[nt][1] * scale + ((kg + 1 > qg0    ) ? 1.f : 0.f);
                s[nt][2] = s[nt][2] * scale + ((kg     > qg0 + 8) ? 1.f : 0.f);
                s[nt][3] = s[nt][3] * scale + ((kg + 1 > qg0 + 8) ? 1.f : 0.f);
            }

            // ---- online softmax (rows g, g+8), packed f16x2 ex2 ----
            uint32_t p2[8][2];   // exp results as half2 == PV A-fragments
            #pragma unroll
            for (int half_i = 0; half_i < 2; half_i++) {
                const int ri = mt * 2 + half_i;
                float tm = -1e30f;
                #pragma unroll
                for (int nt = 0; nt < 8; nt++) {
                    tm = fmaxf(tm, s[nt][2 * half_i]);
                    tm = fmaxf(tm, s[nt][2 * half_i + 1]);
                }
                tm = fmaxf(tm, __shfl_xor_sync(0xffffffffu, tm, 1));
                tm = fmaxf(tm, __shfl_xor_sync(0xffffffffu, tm, 2));
                const float mnew = fmaxf(mrow[ri], tm);
                const float corr = __expf(mrow[ri] - mnew);
                const float mnL  = mnew * L2E;
                float ts = 0.f;
                #pragma unroll
                for (int nt = 0; nt < 8; nt++) {
                    const float a0 = fmaf(s[nt][2 * half_i],     L2E, -mnL);
                    const float a1 = fmaf(s[nt][2 * half_i + 1], L2E, -mnL);
                    __half2 hh = __floats2half2_rn(a0, a1);
                    const uint32_t pe = ex2_f16x2(*(uint32_t*)&hh);
                    p2[nt][half_i] = pe;
                    const float2 f = __half22float2(*(__half2*)&pe);
                    ts += f.x + f.y;
                }
                ts += __shfl_xor_sync(0xffffffffu, ts, 1);
                ts += __shfl_xor_sync(0xffffffffu, ts, 2);
                lrow[ri] = lrow[ri] * corr + ts;
                mrow[ri] = mnew;
                #pragma unroll
                for (int nt = 0; nt < 8; nt++) {
                    o[mt][nt][2 * half_i]     *= corr;
                    o[mt][nt][2 * half_i + 1] *= corr;
                }
            }

            // ---- O += P @ V : p2 used directly as A-fragments ----
            #pragma unroll
            for (int j = 0; j < 4; j++) {
                const uint32_t a0 = p2[2 * j][0];
                const uint32_t a1 = p2[2 * j][1];
                const uint32_t a2 = p2[2 * j + 1][0];
                const uint32_t a3 = p2[2 * j + 1][1];
                #pragma unroll
                for (int nt = 0; nt < 8; nt++) {
                    const int row = nt * 8 + g;
                    const int sw  = nt * 8;           // row & 56 (g < 8)
                    const uint32_t b0 = ldh2(&Vt[row][(j * 16 + 2 * t    ) ^ sw]);
                    const uint32_t b1 = ldh2(&Vt[row][(j * 16 + 2 * t + 8) ^ sw]);
                    mma_f16(o[mt][nt], a0, a1, a2, a3, b0, b1);
                }
            }
        }
        __syncthreads();   // protect Ks/Vt for next tile's store phase
    }

    // ---- epilogue: normalize & store half ----
    #pragma unroll
    for (int mt = 0; mt < 2; mt++) {
        const float inv0 = 1.f / lrow[mt * 2];
        const float inv1 = 1.f / lrow[mt * 2 + 1];
        const int r0 = q0 + warp * 32 + mt * 16 + g;
        #pragma unroll
        for (int nt = 0; nt < 8; nt++) {
            const int c = h * DK + nt * 8 + 2 * t;
            *(__half2*)&O[((size_t)r0 * BATCH + b) * DMODEL + c] =
                __floats2half2_rn(o[mt][nt][0] * inv0, o[mt][nt][1] * inv0);
            *(__half2*)&O[((size_t)(r0 + 8) * BATCH + b) * DMODEL + c] =
                __floats2half2_rn(o[mt][nt][2] * inv1, o[mt][nt][3] * inv1);
        }
    }
}

// ---------------------------------------------------------------------------
// Fused residual-add + LayerNorm; optional half copy of the output.
// ---------------------------------------------------------------------------
__global__ void __launch_bounds__(256)
add_ln_kernel(const float* __restrict__ X, const float* __restrict__ Y,
              const float* __restrict__ gamma, const float* __restrict__ beta,
              float* __restrict__ out, __half* __restrict__ outh)
{
    const int warp = (blockIdx.x * blockDim.x + threadIdx.x) >> 5;
    const int lane = threadIdx.x & 31;
    if (warp >= TTOK) return;

    const float* xr = X + (size_t)warp * DMODEL;
    const float* yr = Y + (size_t)warp * DMODEL;

    float v[16];
    float sum = 0.f;
    #pragma unroll
    for (int i = 0; i < 16; i++) {
        v[i] = xr[lane + i * 32] + yr[lane + i * 32];
        sum += v[i];
    }
    #pragma unroll
    for (int m = 16; m > 0; m >>= 1) sum += __shfl_xor_sync(0xffffffffu, sum, m);
    const float mu = sum * (1.f / DMODEL);

    float var = 0.f;
    #pragma unroll
    for (int i = 0; i < 16; i++) { const float d = v[i] - mu; var = fmaf(d, d, var); }
    #pragma unroll
    for (int m = 16; m > 0; m >>= 1) var += __shfl_xor_sync(0xffffffffu, var, m);
    const float rstd = rsqrtf(var * (1.f / DMODEL) + 1e-5f);

    float* orow = out + (size_t)warp * DMODEL;
    #pragma unroll
    for (int i = 0; i < 16; i++) {
        const int c = lane + i * 32;
        const float val = (v[i] - mu) * rstd * gamma[c] + beta[c];
        orow[c] = val;
        if (outh) outh[(size_t)warp * DMODEL + c] = __float2half_rn(val);
    }
}

// ---------------------------------------------------------------------------
// Launch orchestration: graph fork/join via side streams (frozen from R14).
// ---------------------------------------------------------------------------
extern "C" void kernel_launch(void* const* d_in, const int* in_sizes, int n_in,
                              void* d_out, int out_size)
{
    const float* x     = (const float*)d_in[0];
    const float* Wq    = (const float*)d_in[1];
    const float* bq    = (const float*)d_in[2];
    const float* Wv    = (const float*)d_in[3];
    const float* bv    = (const float*)d_in[4];
    const float* Wr    = (const float*)d_in[5];
    const float* br    = (const float*)d_in[6];
    const float* W_h   = (const float*)d_in[7];
    const float* Wo    = (const float*)d_in[8];
    const float* bo    = (const float*)d_in[9];
    const float* ln1_g = (const float*)d_in[10];
    const float* ln1_b = (const float*)d_in[11];
    const float* Wf1   = (const float*)d_in[12];
    const float* bf1   = (const float*)d_in[13];
    const float* Wf2   = (const float*)d_in[14];
    const float* bf2   = (const float*)d_in[15];
    const float* ln2_g = (const float*)d_in[16];
    const float* ln2_b = (const float*)d_in[17];
    float* out = (float*)d_out;

    static __half *pxh = nullptr, *pQh, *pVh, *pRh, *pHh, *pAh, *px1h, *pFFh,
                  *pWqh, *pWvh, *pWrh, *pWoh, *pW1T, *pW2T;
    static float *pTmp, *pX1;
    static cudaStream_t s1, s2;
    static cudaEvent_t evRoot, evH, evW;
    if (!pxh) {
        cudaGetSymbolAddress((void**)&pxh,  g_xh);
        cudaGetSymbolAddress((void**)&pQh,  g_Qh);
        cudaGetSymbolAddress((void**)&pVh,  g_Vh);
        cudaGetSymbolAddress((void**)&pRh,  g_Rh);
        cudaGetSymbolAddress((void**)&pHh,  g_Hh);
        cudaGetSymbolAddress((void**)&pAh,  g_attnh);
        cudaGetSymbolAddress((void**)&px1h, g_x1h);
        cudaGetSymbolAddress((void**)&pFFh, g_ffh);
        cudaGetSymbolAddress((void**)&pWqh, g_Wqh);
        cudaGetSymbolAddress((void**)&pWvh, g_Wvh);
        cudaGetSymbolAddress((void**)&pWrh, g_Wrh);
        cudaGetSymbolAddress((void**)&pWoh, g_Woh);
        cudaGetSymbolAddress((void**)&pW1T, g_Wf1T);
        cudaGetSymbolAddress((void**)&pW2T, g_Wf2T);
        cudaGetSymbolAddress((void**)&pTmp, g_tmp);
        cudaGetSymbolAddress((void**)&pX1,  g_x1);
        cudaFuncSetAttribute(attn_h, cudaFuncAttributeMaxDynamicSharedMemorySize,
                             ATTN_SMEM);
        cudaFuncSetAttribute(gemm_h<false, true>,
                             cudaFuncAttributeMaxDynamicSharedMemorySize, GEMM_SMEM);
        cudaFuncSetAttribute(gemm_h<false, false>,
                             cudaFuncAttributeMaxDynamicSharedMemorySize, GEMM_SMEM);
        cudaFuncSetAttribute(gemm_h<true, true>,
                             cudaFuncAttributeMaxDynamicSharedMemorySize, GEMM_SMEM);
        cudaStreamCreateWithFlags(&s1, cudaStreamNonBlocking);
        cudaStreamCreateWithFlags(&s2, cudaStreamNonBlocking);
        cudaEventCreateWithFlags(&evRoot, cudaEventDisableTiming);
        cudaEventCreateWithFlags(&evH,    cudaEventDisableTiming);
        cudaEventCreateWithFlags(&evW,    cudaEventDisableTiming);
    }

    const dim3 gP (DMODEL / 128, TTOK / 128);   // (4, 128)
    const dim3 gF1(DFF    / 128, TTOK / 128);   // (16, 128)
    const dim3 gAt(SEQ / 128, BATCH * HEADS);   // (16, 64)
    const dim3 gLN(TTOK / 8, 1);

    // ---- root: conversions needed for R branch + fork point ----
    f2h_kernel<<<(TTOK * DMODEL / 4 + 255) / 256, 256>>>(x, pxh, TTOK * DMODEL);
    f2h_kernel<<<(DMODEL * DMODEL / 4 + 255) / 256, 256>>>(Wr, pWrh, DMODEL * DMODEL);
    cudaEventRecord(evRoot, 0);

    // ---- branch s1: R projection + recurrence -> H ----
    cudaStreamWaitEvent(s1, evRoot, 0);
    gemm_h<false, true><<<gP, 128, GEMM_SMEM, s1>>>(pxh, pWrh, br, pRh,
                                                    TTOK, DMODEL, DMODEL);
    recur_kernel<<<32, 128, 0, s1>>>(pRh, W_h, pHh);
    cudaEventRecord(evH, s1);

    // ---- branch s2: deferred weight conversions ----
    cudaStreamWaitEvent(s2, evRoot, 0);
    f2h_kernel<<<(DMODEL * DMODEL / 4 + 255) / 256, 256, 0, s2>>>(
        Wo, pWoh, DMODEL * DMODEL);
    transpose_h_kernel<<<dim3(DFF / 32, DMODEL / 32), 256, 0, s2>>>(
        Wf1, pW1T, DMODEL, DFF);
    transpose_h_kernel<<<dim3(DMODEL / 32, DFF / 32), 256, 0, s2>>>(
        Wf2, pW2T, DFF, DMODEL);
    cudaEventRecord(evW, s2);

    // ---- main: Q, V projections (concurrent with s1/s2) ----
    f2h_kernel<<<(DMODEL * DMODEL / 4 + 255) / 256, 256>>>(Wq, pWqh, DMODEL * DMODEL);
    f2h_kernel<<<(DMODEL * DMODEL / 4 + 255) / 256, 256>>>(Wv, pWvh, DMODEL * DMODEL);
    gemm_h<false, true><<<gP, 128, GEMM_SMEM>>>(pxh, pWqh, bq, pQh, TTOK, DMODEL, DMODEL);
    gemm_h<false, true><<<gP, 128, GEMM_SMEM>>>(pxh, pWvh, bv, pVh, TTOK, DMODEL, DMODEL);

    // ---- join H, run attention ----
    cudaStreamWaitEvent(0, evH, 0);
    attn_h<<<gAt, 128, ATTN_SMEM>>>(pQh, pHh, pVh, pAh);

    // ---- join weight branch, then the tail chain ----
    cudaStreamWaitEvent(0, evW, 0);
    gemm_h<false, false><<<gP, 128, GEMM_SMEM>>>(pAh, pWoh, bo, pTmp, TTOK, DMODEL, DMODEL);
    add_ln_kernel<<<gLN, 256>>>(x, pTmp, ln1_g, ln1_b, pX1, px1h);
    gemm_h<true, true><<<gF1, 128, GEMM_SMEM>>>(px1h, pW1T, bf1, pFFh, TTOK, DFF, DMODEL);
    gemm_h<false, false><<<gP, 128, GEMM_SMEM>>>(pFFh, pW2T, bf2, pTmp, TTOK, DMODEL, DFF);
    add_ln_kernel<<<gLN, 256>>>(pX1, pTmp, ln2_g, ln2_b, out, nullptr);
}